// round 2
// baseline (speedup 1.0000x reference)
#include <cuda_runtime.h>
#include <mma.h>
#include <cstdint>

using namespace nvcuda;

#define Bn   32
#define Cn   80
#define Fn   2048
#define HWn  1024
#define HIDn 256
#define EDDn 64
#define EINn 259

// output offsets (float32, flattened tuple order)
#define OFF_W    0
#define OFF_AW   6400
#define OFF_DLOG 170240
#define OFF_CAM  170320
#define OFF_REF  2791760
#define OFF_TOT  2794320

// ---------------- scratch (device globals; no allocations) ----------------
__device__ float g_probs[Bn*Cn], g_tgt[Bn*Cn], g_y[Bn*Cn];
__device__ float g_pooled[Bn*Fn];
__device__ float g_wsum[Cn], g_freq[Cn], g_present[Cn], g_P[Bn];
__device__ float g_proto[Cn*Fn], g_pn[Cn*Fn];
__device__ float g_cos[Cn*Cn];
__device__ float g_T1[Cn*HIDn], g_Hn[Cn*HIDn];
__device__ float g_Zd[Cn*EDDn];
__device__ float g_EF[Cn*Cn*EINn];
__device__ float g_E1[Cn*Cn*128];
__device__ float g_E2[Cn*Cn*64];
__device__ float g_r[Cn*Cn], g_h[Cn*Cn], g_A[Cn*Cn];
__device__ float g_AZ[Cn*HIDn], g_M1[Cn*HIDn], g_M2[Cn*HIDn], g_Z[Cn*HIDn];
__device__ float g_awraw[Cn*Fn];
__device__ float g_cam[Bn*Cn*HWn];

// ---------------- helpers ----------------
__device__ __forceinline__ float wredsum(float v){
    #pragma unroll
    for (int o = 16; o; o >>= 1) v += __shfl_xor_sync(0xffffffffu, v, o);
    return v;
}
__device__ __forceinline__ float sigmoidf_(float x){ return 1.f/(1.f+expf(-x)); }
__device__ __forceinline__ float softplusf_(float x){ return fmaxf(x,0.f) + log1pf(expf(-fabsf(x))); }
__device__ __forceinline__ float bcef_(float x, float t){
    return fmaxf(x,0.f) - x*t + log1pf(expf(-fabsf(x)));
}
__device__ __forceinline__ float bredf(float v){
    __shared__ float red[256];
    int t = threadIdx.x;
    red[t] = v; __syncthreads();
    for (int o = 128; o; o >>= 1){ if (t < o) red[t] += red[t+o]; __syncthreads(); }
    float s = red[0]; __syncthreads();
    return s;
}

// ---------------- elementwise / small kernels ----------------
__global__ void k_probs_y(const float* __restrict__ cls, const int* __restrict__ lab){
    int idx = blockIdx.x*256 + threadIdx.x;
    if (idx >= Bn*Cn) return;
    g_probs[idx] = sigmoidf_(cls[idx]);
    float tg = (float)lab[idx];
    g_tgt[idx] = tg;
    g_y[idx] = fmaxf(tg, 0.f);
}

// warp-per-(b,f) row mean over 1024 spatial
__global__ void __launch_bounds__(256) k_pool(const float* __restrict__ feats){
    int w = (blockIdx.x*256 + threadIdx.x) >> 5;
    int lane = threadIdx.x & 31;
    if (w >= Bn*Fn) return;
    const float4* p = reinterpret_cast<const float4*>(feats + (size_t)w*HWn);
    float s = 0.f;
    #pragma unroll
    for (int i = 0; i < 8; i++){ float4 v = p[lane + 32*i]; s += (v.x+v.y)+(v.z+v.w); }
    s = wredsum(s);
    if (!lane) g_pooled[w] = s * (1.f/1024.f);
}

__global__ void k_stats(){
    int t = threadIdx.x;
    if (t < Cn){
        float s = 0.f, mx = 0.f;
        #pragma unroll 4
        for (int b = 0; b < Bn; b++){ s += g_probs[b*Cn+t]; mx = fmaxf(mx, g_y[b*Cn+t]); }
        g_wsum[t] = fmaxf(s, 1e-6f);
        g_freq[t] = s * (1.f/Bn);
        g_present[t] = (mx > 0.f) ? 1.f : 0.f;
    } else if (t < Cn + Bn){
        int b = t - Cn; float s = 0.f;
        for (int c = 0; c < Cn; c++) s += g_probs[b*Cn+c];
        g_P[b] = s;
    }
}

__global__ void k_proto(){
    int c = blockIdx.x;
    __shared__ float sp[Bn];
    if (threadIdx.x < Bn) sp[threadIdx.x] = g_probs[threadIdx.x*Cn + c];
    __syncthreads();
    float inv = 1.f / g_wsum[c];
    for (int f = threadIdx.x; f < Fn; f += 256){
        float a = 0.f;
        #pragma unroll
        for (int b = 0; b < Bn; b++) a += sp[b]*g_pooled[b*Fn+f];
        g_proto[c*Fn+f] = a*inv;
    }
}

__global__ void k_pn(){
    int c = blockIdx.x;
    float s = 0.f;
    for (int f = threadIdx.x; f < Fn; f += 256){ float v = g_proto[c*Fn+f]; s += v*v; }
    s = bredf(s);
    float inv = 1.f / fmaxf(sqrtf(s), 1e-6f);
    for (int f = threadIdx.x; f < Fn; f += 256) g_pn[c*Fn+f] = g_proto[c*Fn+f]*inv;
}

__global__ void k_cos(){
    int i = blockIdx.x;
    int wid = threadIdx.x >> 5, lane = threadIdx.x & 31;
    for (int j = wid; j < Cn; j += 8){
        float s = 0.f;
        for (int k = lane; k < Fn; k += 32) s += g_pn[i*Fn+k]*g_pn[j*Fn+k];
        s = wredsum(s);
        if (!lane) g_cos[i*Cn+j] = fminf(fmaxf(s, -1.f), 1.f);
    }
}

// ---------------- generic small GEMM: out = act(X[MxK] @ W[KxN] + bias) ----
// grid (ceil(N/128), ceil(M/8)), block 128; each thread: 8 M-rows, 1 N-col
template<int ACT>
__global__ void __launch_bounds__(128) gemm_mt8(
        const float* __restrict__ X, const float* __restrict__ W,
        const float* __restrict__ bias, float* __restrict__ out,
        int M, int K, int N){
    int n = blockIdx.x*128 + threadIdx.x;
    int m0 = blockIdx.y*8;
    float acc[8] = {0,0,0,0,0,0,0,0};
    __shared__ float Xs[32][8];
    for (int k0 = 0; k0 < K; k0 += 32){
        int t = threadIdx.x;
        #pragma unroll
        for (int idx = 0; idx < 2; idx++){
            int lin = t + idx*128;
            int i = lin & 7, kk = lin >> 3;
            int m = m0 + i, k = k0 + kk;
            Xs[kk][i] = (m < M && k < K) ? X[(size_t)m*K + k] : 0.f;
        }
        __syncthreads();
        if (n < N){
            int kmax = min(32, K - k0);
            if (kmax == 32){
                #pragma unroll 4
                for (int kk = 0; kk < 32; kk++){
                    float w = W[(size_t)(k0+kk)*N + n];
                    #pragma unroll
                    for (int i = 0; i < 8; i++) acc[i] += Xs[kk][i]*w;
                }
            } else {
                for (int kk = 0; kk < kmax; kk++){
                    float w = W[(size_t)(k0+kk)*N + n];
                    #pragma unroll
                    for (int i = 0; i < 8; i++) acc[i] += Xs[kk][i]*w;
                }
            }
        }
        __syncthreads();
    }
    if (n < N){
        float bv = bias ? bias[n] : 0.f;
        #pragma unroll
        for (int i = 0; i < 8; i++){
            int m = m0 + i;
            if (m >= M) break;
            float v = acc[i] + bv;
            if (ACT == 1) v = fmaxf(v, 0.f);
            if (ACT == 2) v = softplusf_(v);
            out[(size_t)m*N + n] = v;
        }
    }
}

// ---------------- edge pipeline ----------------
__global__ void k_ef(){
    int e = blockIdx.x;              // pair index i*Cn+j
    int i = e / Cn, j = e - i*Cn;
    int t = threadIdx.x;             // 64 threads
    float zi = g_Zd[i*EDDn + t];
    float zj = g_Zd[j*EDDn + t];
    float* o = g_EF + (size_t)e*EINn;
    o[t]        = zi;
    o[64 + t]   = zj;
    o[128 + t]  = fabsf(zi - zj);
    o[192 + t]  = zi * zj;
    if (!t){ o[256] = g_cos[e]; o[257] = g_freq[i]; o[258] = g_freq[j]; }
}

__global__ void k_r(const float* __restrict__ w3, const float* __restrict__ b3,
                    const float* __restrict__ pmi){
    int e = blockIdx.x*8 + (threadIdx.x >> 5);
    int lane = threadIdx.x & 31;
    if (e >= Cn*Cn) return;
    float v = g_E2[(size_t)e*64 + lane]      * w3[lane]
            + g_E2[(size_t)e*64 + 32 + lane] * w3[32 + lane];
    v = wredsum(v);
    if (!lane){
        float r = v + b3[0];
        g_r[e] = r;
        g_h[e] = pmi[e]*(1.f/2.5f) + r;
    }
}

__global__ void k_wadj(float* __restrict__ o_wadj){
    int idx = blockIdx.x*256 + threadIdx.x;
    if (idx >= Cn*Cn) return;
    int i = idx / Cn, j = idx - i*Cn;
    float a = sigmoidf_(g_h[idx]);
    float b = sigmoidf_(g_h[j*Cn + i]);
    o_wadj[idx] = (i == j) ? 0.f : 0.5f*(a + b);
}

__global__ void k_An(const float* __restrict__ wadj){
    int row = (blockIdx.x*256 + threadIdx.x) >> 5;
    int lane = threadIdx.x & 31;
    if (row >= Cn) return;
    float s = 0.f;
    for (int j = lane; j < Cn; j += 32) s += wadj[row*Cn + j];
    s = wredsum(s);
    float inv = 1.f / fmaxf(s, 1e-6f);
    for (int j = lane; j < Cn; j += 32) g_A[row*Cn + j] = wadj[row*Cn + j]*inv;
}

__global__ void k_Zup(){
    int idx = blockIdx.x*256 + threadIdx.x;
    if (idx >= Cn*HIDn) return;
    g_Z[idx] = fmaxf(g_Hn[idx] + g_M2[idx], 0.f);
}

__global__ void k_awnorm(float* __restrict__ o_aw){
    int c = blockIdx.x;
    float s = 0.f;
    for (int f = threadIdx.x; f < Fn; f += 256) s += g_awraw[c*Fn+f];
    s = bredf(s);
    float inv = 1.f / fmaxf(s, 1e-6f);
    for (int f = threadIdx.x; f < Fn; f += 256) o_aw[c*Fn+f] = g_awraw[c*Fn+f]*inv;
}

__global__ void k_dlog(const float* __restrict__ bw, const float* __restrict__ bb,
                       float* __restrict__ o_dlog){
    int t = blockIdx.x*128 + threadIdx.x;
    if (t >= Cn) return;
    float s = 0.f;
    #pragma unroll 8
    for (int k = 0; k < HIDn; k++) s += g_Z[t*HIDn + k]*bw[k];
    o_dlog[t] = s + bb[0];
}

__global__ void k_refined(const float* __restrict__ cls, const float* __restrict__ wadj,
                          const float* __restrict__ dlog, float* __restrict__ o_ref){
    int idx = blockIdx.x*256 + threadIdx.x;
    if (idx >= Bn*Cn) return;
    int b = idx / Cn, d = idx - b*Cn;
    float s = 0.f;
    #pragma unroll 4
    for (int c = 0; c < Cn; c++) s += g_probs[b*Cn+c]*g_y[b*Cn+c]*wadj[c*Cn+d];
    float pos = g_y[idx]*s;
    o_ref[idx] = cls[idx] + 0.5f*pos - 0.25f*(g_P[b] - pos) + dlog[d];
}

// ---------------- cam: tf32 WMMA GEMM  cam[b] = aw[80x2048] @ feats[b][2048x1024]
// block: 256 thr (8 warps), tile 80(M) x 128(N); grid (8 n-tiles, 32 b)
__global__ void __launch_bounds__(256) k_cam(const float* __restrict__ aw,
                                             const float* __restrict__ feats){
    const int b  = blockIdx.y;
    const int n0 = blockIdx.x*128;
    const int t  = threadIdx.x;
    const int wid = t >> 5;
    __shared__ float As[80*36];    // [m][kk], pad 36
    __shared__ float Bs[32*132];   // [kk][n], pad 132
    wmma::fragment<wmma::accumulator,16,16,8,float> acc[5];
    #pragma unroll
    for (int m = 0; m < 5; m++) wmma::fill_fragment(acc[m], 0.f);
    const float* fb = feats + (size_t)b*Fn*HWn;
    for (int k0 = 0; k0 < Fn; k0 += 32){
        #pragma unroll
        for (int rr = 0; rr < 10; rr++){
            int idx = t + rr*256;                 // 0..2559
            int m = idx >> 5, kk = idx & 31;
            As[m*36 + kk] = aw[(size_t)m*Fn + k0 + kk];
        }
        #pragma unroll
        for (int rr = 0; rr < 4; rr++){
            int idx = t + rr*256;                 // 0..1023 float4s
            int kk = idx >> 5, j4 = idx & 31;
            float4 v = *reinterpret_cast<const float4*>(fb + (size_t)(k0+kk)*HWn + n0 + j4*4);
            *reinterpret_cast<float4*>(&Bs[kk*132 + j4*4]) = v;
        }
        __syncthreads();
        #pragma unroll
        for (int ks = 0; ks < 4; ks++){
            wmma::fragment<wmma::matrix_b,16,16,8,wmma::precision::tf32,wmma::row_major> bf;
            wmma::load_matrix_sync(bf, &Bs[ks*8*132 + wid*16], 132);
            #pragma unroll
            for (int e = 0; e < bf.num_elements; e++) bf.x[e] = wmma::__float_to_tf32(bf.x[e]);
            #pragma unroll
            for (int m = 0; m < 5; m++){
                wmma::fragment<wmma::matrix_a,16,16,8,wmma::precision::tf32,wmma::row_major> af;
                wmma::load_matrix_sync(af, &As[m*16*36 + ks*8], 36);
                #pragma unroll
                for (int e = 0; e < af.num_elements; e++) af.x[e] = wmma::__float_to_tf32(af.x[e]);
                wmma::mma_sync(acc[m], af, bf, acc[m]);
            }
        }
        __syncthreads();
    }
    #pragma unroll
    for (int m = 0; m < 5; m++)
        wmma::store_matrix_sync(&g_cam[((size_t)(b*Cn + m*16))*HWn + n0 + wid*16],
                                acc[m], HWn, wmma::mem_row_major);
}

// warp-per-(b,c) row: relu -> minmax -> normalize
__global__ void __launch_bounds__(256) k_camvis(float* __restrict__ o_cam){
    int row = (blockIdx.x*256 + threadIdx.x) >> 5;
    int lane = threadIdx.x & 31;
    if (row >= Bn*Cn) return;
    const float4* p = reinterpret_cast<const float4*>(g_cam + (size_t)row*HWn);
    float vals[32];
    float mn = 1e30f, mx = -1e30f;
    #pragma unroll
    for (int i = 0; i < 8; i++){
        float4 v = p[lane + 32*i];
        float a = fmaxf(v.x, 0.f), b = fmaxf(v.y, 0.f), c = fmaxf(v.z, 0.f), d = fmaxf(v.w, 0.f);
        vals[4*i] = a; vals[4*i+1] = b; vals[4*i+2] = c; vals[4*i+3] = d;
        mn = fminf(mn, fminf(fminf(a,b), fminf(c,d)));
        mx = fmaxf(mx, fmaxf(fmaxf(a,b), fmaxf(c,d)));
    }
    #pragma unroll
    for (int o = 16; o; o >>= 1){
        mn = fminf(mn, __shfl_xor_sync(0xffffffffu, mn, o));
        mx = fmaxf(mx, __shfl_xor_sync(0xffffffffu, mx, o));
    }
    float inv = 1.f / (mx - mn + 1e-6f);
    float4* q = reinterpret_cast<float4*>(o_cam + (size_t)row*HWn);
    #pragma unroll
    for (int i = 0; i < 8; i++){
        float4 v;
        v.x = (vals[4*i]   - mn)*inv;
        v.y = (vals[4*i+1] - mn)*inv;
        v.z = (vals[4*i+2] - mn)*inv;
        v.w = (vals[4*i+3] - mn)*inv;
        q[lane + 32*i] = v;
    }
}

// ---------------- losses (single block) ----------------
__global__ void k_loss(const float* __restrict__ refined, const float* __restrict__ wadj,
                       const float* __restrict__ pmi, float* __restrict__ o_tot){
    int t = threadIdx.x;
    float s_cls = 0.f, msum = 0.f;
    for (int idx = t; idx < Bn*Cn; idx += 256){
        float tg = g_tgt[idx];
        float m = (tg != -1.f) ? 1.f : 0.f;
        float st = (m > 0.f) ? tg : 0.f;
        s_cls += bcef_(refined[idx], st)*m;
        msum += m;
    }
    float spb=0,snb=0,np=0,nn=0,ne=0,sr=0,sw=0;
    for (int idx = t; idx < Cn*Cn; idx += 256){
        int i = idx / Cn, j = idx - i*Cn;
        float emf = (i != j && g_present[i] > 0.f && g_present[j] > 0.f) ? 1.f : 0.f;
        float tt = sigmoidf_(pmi[idx]*(1.f/2.5f));
        float bce = bcef_(g_h[idx], tt);
        float posf = (tt > 0.5f) ? 1.f : 0.f;
        spb += bce*emf*posf;
        snb += bce*emf*(1.f - posf);
        np += posf*emf; nn += (1.f - posf)*emf; ne += emf;
        sr += fabsf(g_r[idx])*emf;
        sw += wadj[idx];
    }
    s_cls = bredf(s_cls); msum = bredf(msum);
    spb = bredf(spb); snb = bredf(snb);
    np = bredf(np); nn = bredf(nn); ne = bredf(ne);
    sr = bredf(sr); sw = bredf(sw);
    if (t == 0){
        float cls_loss = s_cls / fmaxf(msum, 1.f);
        float wp = fminf(fmaxf(fmaxf(nn,1.f)/fmaxf(np,1.f), 1.f), 10.f);
        float ne_ = fmaxf(ne, 1.f);
        float edge_loss = (wp*spb + snb)/ne_;
        float r_reg = 0.001f*sr/ne_;
        float sparsity = sw * (1.f/(Cn*Cn));
        o_tot[0] = cls_loss + 0.1f*edge_loss + r_reg + 0.01f*sparsity;
    }
}

// ---------------- host ----------------
static float* S(const void* sym){ void* p = nullptr; cudaGetSymbolAddress(&p, sym); return (float*)p; }

extern "C" void kernel_launch(void* const* d_in, const int* in_sizes, int n_in,
                              void* d_out, int out_size){
    const float* feats   = (const float*)d_in[0];
    const float* cls     = (const float*)d_in[1];
    const int*   labels  = (const int*)  d_in[2];
    const float* pmi     = (const float*)d_in[3];
    const float* pp_w1   = (const float*)d_in[4];
    const float* pp_b1   = (const float*)d_in[5];
    const float* pp_w2   = (const float*)d_in[6];
    const float* pp_b2   = (const float*)d_in[7];
    const float* msg_w1  = (const float*)d_in[8];
    const float* msg_b1  = (const float*)d_in[9];
    const float* msg_w2  = (const float*)d_in[10];
    const float* msg_b2  = (const float*)d_in[11];
    const float* ed_w    = (const float*)d_in[12];
    const float* ed_b    = (const float*)d_in[13];
    const float* em_w1   = (const float*)d_in[14];
    const float* em_b1   = (const float*)d_in[15];
    const float* em_w2   = (const float*)d_in[16];
    const float* em_b2   = (const float*)d_in[17];
    const float* em_w3   = (const float*)d_in[18];
    const float* em_b3   = (const float*)d_in[19];
    const float* alpha_w = (const float*)d_in[20];
    const float* alpha_b = (const float*)d_in[21];
    const float* bias_w  = (const float*)d_in[22];
    const float* bias_b  = (const float*)d_in[23];

    float* out    = (float*)d_out;
    float* o_wadj = out + OFF_W;
    float* o_aw   = out + OFF_AW;
    float* o_dlog = out + OFF_DLOG;
    float* o_cam  = out + OFF_CAM;
    float* o_ref  = out + OFF_REF;
    float* o_tot  = out + OFF_TOT;

    float* proto = S(g_proto);
    float* T1    = S(g_T1);
    float* Hn    = S(g_Hn);
    float* Zd    = S(g_Zd);
    float* EF    = S(g_EF);
    float* E1    = S(g_E1);
    float* E2    = S(g_E2);
    float* A_    = S(g_A);
    float* AZ    = S(g_AZ);
    float* M1    = S(g_M1);
    float* M2    = S(g_M2);
    float* Zm    = S(g_Z);
    float* awraw = S(g_awraw);

    k_probs_y<<<10, 256>>>(cls, labels);
    k_pool<<<8192, 256>>>(feats);
    k_stats<<<1, 128>>>();
    k_proto<<<80, 256>>>();
    k_pn<<<80, 256>>>();
    k_cos<<<80, 256>>>();

    gemm_mt8<1><<<dim3(2,10), 128>>>(proto, pp_w1, pp_b1, T1, Cn, Fn, HIDn);
    gemm_mt8<0><<<dim3(2,10), 128>>>(T1, pp_w2, pp_b2, Hn, Cn, HIDn, HIDn);
    gemm_mt8<1><<<dim3(1,10), 128>>>(Hn, ed_w, ed_b, Zd, Cn, HIDn, EDDn);

    k_ef<<<Cn*Cn, 64>>>();
    gemm_mt8<1><<<dim3(1,800), 128>>>(EF, em_w1, em_b1, E1, Cn*Cn, EINn, 128);
    gemm_mt8<1><<<dim3(1,800), 128>>>(E1, em_w2, em_b2, E2, Cn*Cn, 128, 64);
    k_r<<<800, 256>>>(em_w3, em_b3, pmi);
    k_wadj<<<25, 256>>>(o_wadj);
    k_An<<<10, 256>>>(o_wadj);

    gemm_mt8<0><<<dim3(2,10), 128>>>(A_, Hn, nullptr, AZ, Cn, Cn, HIDn);
    gemm_mt8<1><<<dim3(2,10), 128>>>(AZ, msg_w1, msg_b1, M1, Cn, HIDn, HIDn);
    gemm_mt8<0><<<dim3(2,10), 128>>>(M1, msg_w2, msg_b2, M2, Cn, HIDn, HIDn);
    k_Zup<<<80, 256>>>();

    gemm_mt8<2><<<dim3(16,10), 128>>>(Zm, alpha_w, alpha_b, awraw, Cn, HIDn, Fn);
    k_awnorm<<<80, 256>>>(o_aw);
    k_dlog<<<1, 128>>>(bias_w, bias_b, o_dlog);
    k_refined<<<10, 256>>>(cls, o_wadj, o_dlog, o_ref);

    k_cam<<<dim3(8, 32), 256>>>(o_aw, feats);
    k_camvis<<<320, 256>>>(o_cam);
    k_loss<<<1, 256>>>(o_ref, o_wadj, pmi, o_tot);

    (void)in_sizes; (void)n_in; (void)out_size;
}

// round 3
// speedup vs baseline: 1.0827x; 1.0827x over previous
#include <cuda_runtime.h>
#include <mma.h>
#include <cstdint>

using namespace nvcuda;

#define Bn   32
#define Cn   80
#define Fn   2048
#define HWn  1024
#define HIDn 256
#define EDDn 64
#define EINn 259

// output offsets (float32, flattened tuple order)
#define OFF_W    0
#define OFF_AW   6400
#define OFF_DLOG 170240
#define OFF_CAM  170320
#define OFF_REF  2791760
#define OFF_TOT  2794320

// ---------------- scratch (device globals; no allocations) ----------------
__device__ float g_probs[Bn*Cn], g_tgt[Bn*Cn], g_y[Bn*Cn];
__device__ float g_pooled[Bn*Fn];
__device__ float g_wsum[Cn], g_freq[Cn], g_present[Cn], g_P[Bn];
__device__ float g_proto[Cn*Fn];
__device__ float g_ninv[Cn];
__device__ float g_cos[Cn*Cn];
__device__ float g_T1[Cn*HIDn], g_Hn[Cn*HIDn];
__device__ float g_Zd[Cn*EDDn];
__device__ float g_r[Cn*Cn], g_h[Cn*Cn], g_A[Cn*Cn];
__device__ float g_Z[Cn*HIDn];
__device__ float g_awraw[Cn*Fn];
__device__ float g_cam[Bn*Cn*HWn];

// ---------------- helpers ----------------
__device__ __forceinline__ float wredsum(float v){
    #pragma unroll
    for (int o = 16; o; o >>= 1) v += __shfl_xor_sync(0xffffffffu, v, o);
    return v;
}
__device__ __forceinline__ float sigmoidf_(float x){ return 1.f/(1.f+expf(-x)); }
__device__ __forceinline__ float softplusf_(float x){ return fmaxf(x,0.f) + log1pf(expf(-fabsf(x))); }
__device__ __forceinline__ float bcef_(float x, float t){
    return fmaxf(x,0.f) - x*t + log1pf(expf(-fabsf(x)));
}
__device__ __forceinline__ float bredf(float v){
    __shared__ float red[256];
    int t = threadIdx.x;
    red[t] = v; __syncthreads();
    for (int o = 128; o; o >>= 1){ if (t < o) red[t] += red[t+o]; __syncthreads(); }
    float s = red[0]; __syncthreads();
    return s;
}

// ---------------- fused prelude: probs/tgt/y + stats (1 block) ----------------
__global__ void __launch_bounds__(256) k_pre(const float* __restrict__ cls,
                                             const int* __restrict__ lab){
    int t = threadIdx.x;
    for (int idx = t; idx < Bn*Cn; idx += 256){
        g_probs[idx] = sigmoidf_(cls[idx]);
        float tg = (float)lab[idx];
        g_tgt[idx] = tg;
        g_y[idx] = fmaxf(tg, 0.f);
    }
    __syncthreads();
    if (t < Cn){
        float s = 0.f, mx = 0.f;
        #pragma unroll 4
        for (int b = 0; b < Bn; b++){ s += g_probs[b*Cn+t]; mx = fmaxf(mx, g_y[b*Cn+t]); }
        g_wsum[t] = fmaxf(s, 1e-6f);
        g_freq[t] = s * (1.f/Bn);
        g_present[t] = (mx > 0.f) ? 1.f : 0.f;
    } else if (t < Cn + Bn){
        int b = t - Cn; float s = 0.f;
        for (int c = 0; c < Cn; c++) s += g_probs[b*Cn+c];
        g_P[b] = s;
    }
}

// warp-per-(b,f) row mean over 1024 spatial (DRAM-roofline)
__global__ void __launch_bounds__(256) k_pool(const float* __restrict__ feats){
    int w = (blockIdx.x*256 + threadIdx.x) >> 5;
    int lane = threadIdx.x & 31;
    if (w >= Bn*Fn) return;
    const float4* p = reinterpret_cast<const float4*>(feats + (size_t)w*HWn);
    float s = 0.f;
    #pragma unroll
    for (int i = 0; i < 8; i++){ float4 v = p[lane + 32*i]; s += (v.x+v.y)+(v.z+v.w); }
    s = wredsum(s);
    if (!lane) g_pooled[w] = s * (1.f/1024.f);
}

// f-parallel prototypes: grid 32 x 64 threads, one f per thread
__global__ void __launch_bounds__(64) k_proto_t(){
    __shared__ float sp[Bn*Cn];      // probs [b][c]
    __shared__ float sinv[Cn];
    int t = threadIdx.x;
    for (int idx = t; idx < Bn*Cn; idx += 64) sp[idx] = g_probs[idx];
    for (int idx = t; idx < Cn; idx += 64) sinv[idx] = 1.f / g_wsum[idx];
    __syncthreads();
    int f = blockIdx.x*64 + t;
    float p[Bn];
    #pragma unroll
    for (int b = 0; b < Bn; b++) p[b] = g_pooled[b*Fn + f];
    for (int c = 0; c < Cn; c++){
        float a = 0.f;
        #pragma unroll
        for (int b = 0; b < Bn; b++) a += sp[b*Cn + c]*p[b];
        g_proto[c*Fn + f] = a * sinv[c];
    }
}

// row norms: warp per class row
__global__ void __launch_bounds__(256) k_norm(){
    int row = blockIdx.x*8 + (threadIdx.x >> 5);
    int lane = threadIdx.x & 31;
    if (row >= Cn) return;
    const float* pr = g_proto + (size_t)row*Fn;
    float s = 0.f;
    for (int k = lane; k < Fn; k += 32){ float v = pr[k]; s += v*v; }
    s = wredsum(s);
    if (!lane) g_ninv[row] = 1.f / fmaxf(sqrtf(s), 1e-6f);
}

// cos[i,j] = clip(dot(proto_i,proto_j)*ninv_i*ninv_j)
__global__ void __launch_bounds__(256) k_cosG(){
    int i = blockIdx.x;
    __shared__ float srow[Fn];
    int t = threadIdx.x;
    #pragma unroll
    for (int k = 0; k < 8; k++) srow[t + 256*k] = g_proto[(size_t)i*Fn + t + 256*k];
    __syncthreads();
    int wid = t >> 5, lane = t & 31;
    float ni = g_ninv[i];
    for (int j = wid; j < Cn; j += 8){
        const float* pj = g_proto + (size_t)j*Fn;
        float s = 0.f;
        for (int k = lane; k < Fn; k += 32) s += srow[k]*pj[k];
        s = wredsum(s);
        if (!lane) g_cos[i*Cn+j] = fminf(fmaxf(s*ni*g_ninv[j], -1.f), 1.f);
    }
}

// ---------------- generic small GEMM: out = act(X[MxK] @ W[KxN] + bias) ----
template<int ACT>
__global__ void __launch_bounds__(128) gemm_mt8(
        const float* __restrict__ X, const float* __restrict__ W,
        const float* __restrict__ bias, float* __restrict__ out,
        int M, int K, int N){
    int n = blockIdx.x*128 + threadIdx.x;
    int m0 = blockIdx.y*8;
    float acc[8] = {0,0,0,0,0,0,0,0};
    __shared__ float Xs[32][8];
    for (int k0 = 0; k0 < K; k0 += 32){
        int t = threadIdx.x;
        #pragma unroll
        for (int idx = 0; idx < 2; idx++){
            int lin = t + idx*128;
            int i = lin & 7, kk = lin >> 3;
            int m = m0 + i, k = k0 + kk;
            Xs[kk][i] = (m < M && k < K) ? X[(size_t)m*K + k] : 0.f;
        }
        __syncthreads();
        if (n < N){
            int kmax = min(32, K - k0);
            if (kmax == 32){
                #pragma unroll 4
                for (int kk = 0; kk < 32; kk++){
                    float w = W[(size_t)(k0+kk)*N + n];
                    #pragma unroll
                    for (int i = 0; i < 8; i++) acc[i] += Xs[kk][i]*w;
                }
            } else {
                for (int kk = 0; kk < kmax; kk++){
                    float w = W[(size_t)(k0+kk)*N + n];
                    #pragma unroll
                    for (int i = 0; i < 8; i++) acc[i] += Xs[kk][i]*w;
                }
            }
        }
        __syncthreads();
    }
    if (n < N){
        float bv = bias ? bias[n] : 0.f;
        #pragma unroll
        for (int i = 0; i < 8; i++){
            int m = m0 + i;
            if (m >= M) break;
            float v = acc[i] + bv;
            if (ACT == 1) v = fmaxf(v, 0.f);
            if (ACT == 2) v = softplusf_(v);
            out[(size_t)m*N + n] = v;
        }
    }
}

// ---------------- fused edge MLP: 16 edges per block, 400 blocks ----------------
__global__ void __launch_bounds__(256) k_edge(
        const float* __restrict__ em_w1, const float* __restrict__ em_b1,
        const float* __restrict__ em_w2, const float* __restrict__ em_b2,
        const float* __restrict__ em_w3, const float* __restrict__ em_b3,
        const float* __restrict__ pmi){
    __shared__ float ef[16][260];
    __shared__ float e1[16][128];
    __shared__ float e2[16][64];
    int t = threadIdx.x;
    int e0 = blockIdx.x*16;
    // build edge features
    #pragma unroll
    for (int rep = 0; rep < 4; rep++){
        int eo = rep*4 + (t >> 6);
        int l = t & 63;
        int e = e0 + eo, i = e/Cn, j = e - i*Cn;
        float zi = g_Zd[i*EDDn + l];
        float zj = g_Zd[j*EDDn + l];
        ef[eo][l]       = zi;
        ef[eo][64 + l]  = zj;
        ef[eo][128 + l] = fabsf(zi - zj);
        ef[eo][192 + l] = zi*zj;
        if (!l){ ef[eo][256] = g_cos[e]; ef[eo][257] = g_freq[i]; ef[eo][258] = g_freq[j]; }
    }
    __syncthreads();
    // layer1: 259 -> 128
    {
        int n = t & 127, eg = t >> 7;          // 2 groups of 8 edges
        float acc[8];
        float bv = em_b1[n];
        #pragma unroll
        for (int q = 0; q < 8; q++) acc[q] = bv;
        for (int k = 0; k < EINn; k++){
            float w = em_w1[(size_t)k*128 + n];
            #pragma unroll
            for (int q = 0; q < 8; q++) acc[q] += ef[eg*8 + q][k]*w;
        }
        #pragma unroll
        for (int q = 0; q < 8; q++) e1[eg*8 + q][n] = fmaxf(acc[q], 0.f);
    }
    __syncthreads();
    // layer2: 128 -> 64
    {
        int n = t & 63, eg = t >> 6;           // 4 groups of 4 edges
        float acc[4];
        float bv = em_b2[n];
        #pragma unroll
        for (int q = 0; q < 4; q++) acc[q] = bv;
        for (int k = 0; k < 128; k++){
            float w = em_w2[(size_t)k*64 + n];
            #pragma unroll
            for (int q = 0; q < 4; q++) acc[q] += e1[eg*4 + q][k]*w;
        }
        #pragma unroll
        for (int q = 0; q < 4; q++) e2[eg*4 + q][n] = fmaxf(acc[q], 0.f);
    }
    __syncthreads();
    // layer3: 64 -> 1, warp handles 2 edges
    {
        int wid = t >> 5, lane = t & 31;
        #pragma unroll
        for (int s2 = 0; s2 < 2; s2++){
            int eo = wid*2 + s2;
            float v = e2[eo][lane]*em_w3[lane] + e2[eo][32+lane]*em_w3[32+lane];
            v = wredsum(v);
            if (!lane){
                int e = e0 + eo;
                float r = v + em_b3[0];
                g_r[e] = r;
                g_h[e] = pmi[e]*(1.f/2.5f) + r;
            }
        }
    }
}

// wadj + row-normalized A, warp per row
__global__ void __launch_bounds__(256) k_wadjAn(float* __restrict__ o_wadj){
    int i = blockIdx.x*8 + (threadIdx.x >> 5);
    int lane = threadIdx.x & 31;
    if (i >= Cn) return;
    float w[3]; int js[3];
    float s = 0.f;
    #pragma unroll
    for (int q = 0; q < 3; q++){
        int j = lane + q*32;
        js[q] = j;
        float v = 0.f;
        if (j < Cn && j != i){
            float a = sigmoidf_(g_h[i*Cn+j]);
            float b = sigmoidf_(g_h[j*Cn+i]);
            v = 0.5f*(a + b);
        }
        w[q] = v; s += v;
    }
    s = wredsum(s);
    float inv = 1.f / fmaxf(s, 1e-6f);
    #pragma unroll
    for (int q = 0; q < 3; q++){
        int j = js[q];
        if (j < Cn){
            o_wadj[i*Cn+j] = w[q];
            g_A[i*Cn+j] = w[q]*inv;
        }
    }
}

// fused GNN step: Z = relu(Hn + (relu((A@Hn)@w1+b1)@w2+b2)), block per row
__global__ void __launch_bounds__(256) k_msg(
        const float* __restrict__ w1, const float* __restrict__ b1,
        const float* __restrict__ w2, const float* __restrict__ b2){
    int i = blockIdx.x;
    int n = threadIdx.x;
    __shared__ float sA[Cn];
    __shared__ float az[HIDn];
    __shared__ float m1[HIDn];
    if (n < Cn) sA[n] = g_A[i*Cn + n];
    __syncthreads();
    float acc = 0.f;
    for (int j = 0; j < Cn; j++) acc += sA[j]*g_Hn[j*HIDn + n];
    az[n] = acc;
    __syncthreads();
    acc = b1[n];
    #pragma unroll 4
    for (int k = 0; k < HIDn; k++) acc += az[k]*w1[(size_t)k*HIDn + n];
    m1[n] = fmaxf(acc, 0.f);
    __syncthreads();
    acc = b2[n];
    #pragma unroll 4
    for (int k = 0; k < HIDn; k++) acc += m1[k]*w2[(size_t)k*HIDn + n];
    g_Z[i*HIDn + n] = fmaxf(g_Hn[i*HIDn + n] + acc, 0.f);
}

__global__ void __launch_bounds__(256) k_awnorm(float* __restrict__ o_aw){
    int c = blockIdx.x;
    float s = 0.f;
    for (int f = threadIdx.x; f < Fn; f += 256) s += g_awraw[c*Fn+f];
    s = bredf(s);
    float inv = 1.f / fmaxf(s, 1e-6f);
    for (int f = threadIdx.x; f < Fn; f += 256) o_aw[c*Fn+f] = g_awraw[c*Fn+f]*inv;
}

// fused dlog + refined: block per class d
__global__ void __launch_bounds__(256) k_dlogref(
        const float* __restrict__ cls, const float* __restrict__ wadj,
        const float* __restrict__ bw, const float* __restrict__ bb,
        float* __restrict__ o_dlog, float* __restrict__ o_ref){
    int d = blockIdx.x;
    int t = threadIdx.x;
    __shared__ float sdlog;
    float v = g_Z[d*HIDn + t]*bw[t];
    v = bredf(v);
    if (!t){ sdlog = v + bb[0]; o_dlog[d] = sdlog; }
    __syncthreads();
    float dl = sdlog;
    int wid = t >> 5, lane = t & 31;
    for (int b = wid; b < Bn; b += 8){
        float s = 0.f;
        for (int c = lane; c < Cn; c += 32)
            s += g_probs[b*Cn+c]*g_y[b*Cn+c]*wadj[c*Cn+d];
        s = wredsum(s);
        if (!lane){
            int idx = b*Cn + d;
            float pos = g_y[idx]*s;
            o_ref[idx] = cls[idx] + 0.5f*pos - 0.25f*(g_P[b] - pos) + dl;
        }
    }
}

// ---------------- cam: tf32 WMMA GEMM  cam[b] = aw[80x2048] @ feats[b][2048x1024]
__global__ void __launch_bounds__(256) k_cam(const float* __restrict__ aw,
                                             const float* __restrict__ feats){
    const int b  = blockIdx.y;
    const int n0 = blockIdx.x*128;
    const int t  = threadIdx.x;
    const int wid = t >> 5;
    __shared__ float As[80*36];    // [m][kk], pad 36
    __shared__ float Bs[32*132];   // [kk][n], pad 132
    wmma::fragment<wmma::accumulator,16,16,8,float> acc[5];
    #pragma unroll
    for (int m = 0; m < 5; m++) wmma::fill_fragment(acc[m], 0.f);
    const float* fb = feats + (size_t)b*Fn*HWn;
    for (int k0 = 0; k0 < Fn; k0 += 32){
        #pragma unroll
        for (int rr = 0; rr < 10; rr++){
            int idx = t + rr*256;
            int m = idx >> 5, kk = idx & 31;
            As[m*36 + kk] = aw[(size_t)m*Fn + k0 + kk];
        }
        #pragma unroll
        for (int rr = 0; rr < 4; rr++){
            int idx = t + rr*256;
            int kk = idx >> 5, j4 = idx & 31;
            float4 v = *reinterpret_cast<const float4*>(fb + (size_t)(k0+kk)*HWn + n0 + j4*4);
            *reinterpret_cast<float4*>(&Bs[kk*132 + j4*4]) = v;
        }
        __syncthreads();
        #pragma unroll
        for (int ks = 0; ks < 4; ks++){
            wmma::fragment<wmma::matrix_b,16,16,8,wmma::precision::tf32,wmma::row_major> bf;
            wmma::load_matrix_sync(bf, &Bs[ks*8*132 + wid*16], 132);
            #pragma unroll
            for (int e = 0; e < bf.num_elements; e++) bf.x[e] = wmma::__float_to_tf32(bf.x[e]);
            #pragma unroll
            for (int m = 0; m < 5; m++){
                wmma::fragment<wmma::matrix_a,16,16,8,wmma::precision::tf32,wmma::row_major> af;
                wmma::load_matrix_sync(af, &As[m*16*36 + ks*8], 36);
                #pragma unroll
                for (int e = 0; e < af.num_elements; e++) af.x[e] = wmma::__float_to_tf32(af.x[e]);
                wmma::mma_sync(acc[m], af, bf, acc[m]);
            }
        }
        __syncthreads();
    }
    #pragma unroll
    for (int m = 0; m < 5; m++)
        wmma::store_matrix_sync(&g_cam[((size_t)(b*Cn + m*16))*HWn + n0 + wid*16],
                                acc[m], HWn, wmma::mem_row_major);
}

// warp-per-(b,c) row: relu -> minmax -> normalize
__global__ void __launch_bounds__(256) k_camvis(float* __restrict__ o_cam){
    int row = (blockIdx.x*256 + threadIdx.x) >> 5;
    int lane = threadIdx.x & 31;
    if (row >= Bn*Cn) return;
    const float4* p = reinterpret_cast<const float4*>(g_cam + (size_t)row*HWn);
    float vals[32];
    float mn = 1e30f, mx = -1e30f;
    #pragma unroll
    for (int i = 0; i < 8; i++){
        float4 v = p[lane + 32*i];
        float a = fmaxf(v.x, 0.f), b = fmaxf(v.y, 0.f), c = fmaxf(v.z, 0.f), d = fmaxf(v.w, 0.f);
        vals[4*i] = a; vals[4*i+1] = b; vals[4*i+2] = c; vals[4*i+3] = d;
        mn = fminf(mn, fminf(fminf(a,b), fminf(c,d)));
        mx = fmaxf(mx, fmaxf(fmaxf(a,b), fmaxf(c,d)));
    }
    #pragma unroll
    for (int o = 16; o; o >>= 1){
        mn = fminf(mn, __shfl_xor_sync(0xffffffffu, mn, o));
        mx = fmaxf(mx, __shfl_xor_sync(0xffffffffu, mx, o));
    }
    float inv = 1.f / (mx - mn + 1e-6f);
    float4* q = reinterpret_cast<float4*>(o_cam + (size_t)row*HWn);
    #pragma unroll
    for (int i = 0; i < 8; i++){
        float4 v;
        v.x = (vals[4*i]   - mn)*inv;
        v.y = (vals[4*i+1] - mn)*inv;
        v.z = (vals[4*i+2] - mn)*inv;
        v.w = (vals[4*i+3] - mn)*inv;
        q[lane + 32*i] = v;
    }
}

// ---------------- losses (single block) ----------------
__global__ void __launch_bounds__(256) k_loss(
        const float* __restrict__ refined, const float* __restrict__ wadj,
        const float* __restrict__ pmi, float* __restrict__ o_tot){
    int t = threadIdx.x;
    float s_cls = 0.f, msum = 0.f;
    for (int idx = t; idx < Bn*Cn; idx += 256){
        float tg = g_tgt[idx];
        float m = (tg != -1.f) ? 1.f : 0.f;
        float st = (m > 0.f) ? tg : 0.f;
        s_cls += bcef_(refined[idx], st)*m;
        msum += m;
    }
    float spb=0,snb=0,np=0,nn=0,ne=0,sr=0,sw=0;
    for (int idx = t; idx < Cn*Cn; idx += 256){
        int i = idx / Cn, j = idx - i*Cn;
        float emf = (i != j && g_present[i] > 0.f && g_present[j] > 0.f) ? 1.f : 0.f;
        float tt = sigmoidf_(pmi[idx]*(1.f/2.5f));
        float bce = bcef_(g_h[idx], tt);
        float posf = (tt > 0.5f) ? 1.f : 0.f;
        spb += bce*emf*posf;
        snb += bce*emf*(1.f - posf);
        np += posf*emf; nn += (1.f - posf)*emf; ne += emf;
        sr += fabsf(g_r[idx])*emf;
        sw += wadj[idx];
    }
    s_cls = bredf(s_cls); msum = bredf(msum);
    spb = bredf(spb); snb = bredf(snb);
    np = bredf(np); nn = bredf(nn); ne = bredf(ne);
    sr = bredf(sr); sw = bredf(sw);
    if (t == 0){
        float cls_loss = s_cls / fmaxf(msum, 1.f);
        float wp = fminf(fmaxf(fmaxf(nn,1.f)/fmaxf(np,1.f), 1.f), 10.f);
        float ne_ = fmaxf(ne, 1.f);
        float edge_loss = (wp*spb + snb)/ne_;
        float r_reg = 0.001f*sr/ne_;
        float sparsity = sw * (1.f/(Cn*Cn));
        o_tot[0] = cls_loss + 0.1f*edge_loss + r_reg + 0.01f*sparsity;
    }
}

// ---------------- host ----------------
static float* S(const void* sym){ void* p = nullptr; cudaGetSymbolAddress(&p, sym); return (float*)p; }

extern "C" void kernel_launch(void* const* d_in, const int* in_sizes, int n_in,
                              void* d_out, int out_size){
    const float* feats   = (const float*)d_in[0];
    const float* cls     = (const float*)d_in[1];
    const int*   labels  = (const int*)  d_in[2];
    const float* pmi     = (const float*)d_in[3];
    const float* pp_w1   = (const float*)d_in[4];
    const float* pp_b1   = (const float*)d_in[5];
    const float* pp_w2   = (const float*)d_in[6];
    const float* pp_b2   = (const float*)d_in[7];
    const float* msg_w1  = (const float*)d_in[8];
    const float* msg_b1  = (const float*)d_in[9];
    const float* msg_w2  = (const float*)d_in[10];
    const float* msg_b2  = (const float*)d_in[11];
    const float* ed_w    = (const float*)d_in[12];
    const float* ed_b    = (const float*)d_in[13];
    const float* em_w1   = (const float*)d_in[14];
    const float* em_b1   = (const float*)d_in[15];
    const float* em_w2   = (const float*)d_in[16];
    const float* em_b2   = (const float*)d_in[17];
    const float* em_w3   = (const float*)d_in[18];
    const float* em_b3   = (const float*)d_in[19];
    const float* alpha_w = (const float*)d_in[20];
    const float* alpha_b = (const float*)d_in[21];
    const float* bias_w  = (const float*)d_in[22];
    const float* bias_b  = (const float*)d_in[23];

    float* out    = (float*)d_out;
    float* o_wadj = out + OFF_W;
    float* o_aw   = out + OFF_AW;
    float* o_dlog = out + OFF_DLOG;
    float* o_cam  = out + OFF_CAM;
    float* o_ref  = out + OFF_REF;
    float* o_tot  = out + OFF_TOT;

    float* proto = S(g_proto);
    float* T1    = S(g_T1);
    float* Hn    = S(g_Hn);
    float* Zd    = S(g_Zd);
    float* Zm    = S(g_Z);
    float* awraw = S(g_awraw);

    k_pre<<<1, 256>>>(cls, labels);
    k_pool<<<8192, 256>>>(feats);
    k_proto_t<<<32, 64>>>();
    k_norm<<<10, 256>>>();
    k_cosG<<<80, 256>>>();

    gemm_mt8<1><<<dim3(2,10), 128>>>(proto, pp_w1, pp_b1, T1, Cn, Fn, HIDn);
    gemm_mt8<0><<<dim3(2,10), 128>>>(T1, pp_w2, pp_b2, Hn, Cn, HIDn, HIDn);
    gemm_mt8<1><<<dim3(1,10), 128>>>(Hn, ed_w, ed_b, Zd, Cn, HIDn, EDDn);

    k_edge<<<400, 256>>>(em_w1, em_b1, em_w2, em_b2, em_w3, em_b3, pmi);
    k_wadjAn<<<10, 256>>>(o_wadj);
    k_msg<<<80, 256>>>(msg_w1, msg_b1, msg_w2, msg_b2);

    gemm_mt8<2><<<dim3(16,10), 128>>>(Zm, alpha_w, alpha_b, awraw, Cn, HIDn, Fn);
    k_awnorm<<<80, 256>>>(o_aw);
    k_dlogref<<<80, 256>>>(cls, o_wadj, bias_w, bias_b, o_dlog, o_ref);

    k_cam<<<dim3(8, 32), 256>>>(o_aw, feats);
    k_camvis<<<320, 256>>>(o_cam);
    k_loss<<<1, 256>>>(o_ref, o_wadj, pmi, o_tot);

    (void)in_sizes; (void)n_in; (void)out_size;
}

// round 4
// speedup vs baseline: 1.3972x; 1.2905x over previous
#include <cuda_runtime.h>
#include <mma.h>
#include <cstdint>

using namespace nvcuda;

#define Bn   32
#define Cn   80
#define Fn   2048
#define HWn  1024
#define HIDn 256
#define EDDn 64
#define EINn 259

#define G    128
#define T    256
#define NT   (G*T)
#define NWARP (NT/32)

// output offsets (float32, flattened tuple order)
#define OFF_W    0
#define OFF_AW   6400
#define OFF_DLOG 170240
#define OFF_CAM  170320
#define OFF_REF  2791760
#define OFF_TOT  2794320

// ---------------- scratch (device globals; no allocations) ----------------
__device__ float g_probs[Bn*Cn], g_tgt[Bn*Cn], g_y[Bn*Cn];
__device__ float g_pooled[Bn*Fn];
__device__ float g_wsum[Cn], g_freq[Cn], g_present[Cn], g_P[Bn];
__device__ float g_proto[Cn*Fn];
__device__ float g_ninv[Cn];
__device__ float g_cos[Cn*Cn];
__device__ float g_part[8*Cn*HIDn];
__device__ float g_T1[Cn*HIDn], g_Hn[Cn*HIDn];
__device__ float g_Zd[Cn*EDDn];
__device__ float g_r[Cn*Cn], g_h[Cn*Cn], g_A[Cn*Cn];
__device__ float g_Z[Cn*HIDn];
__device__ float g_awraw[Cn*Fn];
__device__ float g_cam[Bn*Cn*HWn];

// grid barrier state (monotonic generation -> re-entrant across replays)
__device__ volatile unsigned g_genv;
__device__ unsigned g_cntv;

// ---------------- helpers ----------------
__device__ __forceinline__ float wredsum(float v){
    #pragma unroll
    for (int o = 16; o; o >>= 1) v += __shfl_xor_sync(0xffffffffu, v, o);
    return v;
}
__device__ __forceinline__ float sigmoidf_(float x){ return 1.f/(1.f+expf(-x)); }
__device__ __forceinline__ float softplusf_(float x){ return fmaxf(x,0.f) + log1pf(expf(-fabsf(x))); }
__device__ __forceinline__ float bcef_(float x, float t){
    return fmaxf(x,0.f) - x*t + log1pf(expf(-fabsf(x)));
}

__device__ __forceinline__ void gsync(){
    __syncthreads();
    if (threadIdx.x == 0){
        unsigned my = g_genv;          // read BEFORE arrive
        __threadfence();               // release my writes; order the read
        if (atomicAdd(&g_cntv, 1u) == (unsigned)(G - 1)){
            atomicExch(&g_cntv, 0u);
            __threadfence();
            g_genv = my + 1u;
        } else {
            while (g_genv == my) { }
        }
        __threadfence();               // acquire
    }
    __syncthreads();
}

// block-level reduction into sm[0..T)
__device__ __forceinline__ float bred_sm(float v, float* red){
    int t = threadIdx.x;
    red[t] = v; __syncthreads();
    for (int o = T/2; o; o >>= 1){ if (t < o) red[t] += red[t+o]; __syncthreads(); }
    float s = red[0]; __syncthreads();
    return s;
}

// ============================ MEGA KERNEL ============================
__global__ void __launch_bounds__(T) k_mega(
    const float* __restrict__ feats, const float* __restrict__ cls,
    const int*   __restrict__ lab,   const float* __restrict__ pmi,
    const float* __restrict__ pp_w1, const float* __restrict__ pp_b1,
    const float* __restrict__ pp_w2, const float* __restrict__ pp_b2,
    const float* __restrict__ msg_w1, const float* __restrict__ msg_b1,
    const float* __restrict__ msg_w2, const float* __restrict__ msg_b2,
    const float* __restrict__ ed_w,  const float* __restrict__ ed_b,
    const float* __restrict__ em_w1, const float* __restrict__ em_b1,
    const float* __restrict__ em_w2, const float* __restrict__ em_b2,
    const float* __restrict__ em_w3, const float* __restrict__ em_b3,
    const float* __restrict__ alpha_w, const float* __restrict__ alpha_b,
    const float* __restrict__ bw,    const float* __restrict__ bb,
    float* __restrict__ o_wadj, float* __restrict__ o_aw,
    float* __restrict__ o_dlog, float* __restrict__ o_ref, float* __restrict__ o_tot)
{
    __shared__ float sm[8448];   // 33 KB scratch, reused per phase
    const int tid  = threadIdx.x;
    const int bid  = blockIdx.x;
    const int g    = bid*T + tid;
    const int gw   = g >> 5;
    const int lane = tid & 31;

    // ---- P0: probs/tgt/y + adaptive pool ----
    for (int idx = g; idx < Bn*Cn; idx += NT){
        g_probs[idx] = sigmoidf_(cls[idx]);
        float tg = (float)lab[idx];
        g_tgt[idx] = tg;
        g_y[idx] = fmaxf(tg, 0.f);
    }
    for (int row = gw; row < Bn*Fn; row += NWARP){
        const float4* p = reinterpret_cast<const float4*>(feats + (size_t)row*HWn);
        float s = 0.f;
        #pragma unroll
        for (int i = 0; i < 8; i++){ float4 v = p[lane + 32*i]; s += (v.x+v.y)+(v.z+v.w); }
        s = wredsum(s);
        if (!lane) g_pooled[row] = s * (1.f/1024.f);
    }
    gsync();

    // ---- P1: stats ----
    if (g < Cn){
        float s = 0.f, mx = 0.f;
        #pragma unroll 4
        for (int b = 0; b < Bn; b++){ s += g_probs[b*Cn+g]; mx = fmaxf(mx, g_y[b*Cn+g]); }
        g_wsum[g] = fmaxf(s, 1e-6f);
        g_freq[g] = s * (1.f/Bn);
        g_present[g] = (mx > 0.f) ? 1.f : 0.f;
    } else if (g < Cn + Bn){
        int b = g - Cn; float s = 0.f;
        for (int c = 0; c < Cn; c++) s += g_probs[b*Cn+c];
        g_P[b] = s;
    }
    gsync();

    // ---- P2: prototypes (f-parallel; probs staged in smem) ----
    for (int idx = tid; idx < Bn*Cn; idx += T) sm[idx] = g_probs[idx];
    for (int idx = tid; idx < Cn;   idx += T) sm[Bn*Cn + idx] = 1.f / g_wsum[idx];
    __syncthreads();
    for (int idx = g; idx < Cn*Fn; idx += NT){
        int f = idx & (Fn-1), c = idx >> 11;
        float a = 0.f;
        #pragma unroll
        for (int b = 0; b < Bn; b++) a += sm[b*Cn + c]*g_pooled[b*Fn + f];
        g_proto[idx] = a * sm[Bn*Cn + c];
    }
    gsync();

    // ---- P3: row inv-norms ----
    for (int row = gw; row < Cn; row += NWARP){
        const float4* pr = reinterpret_cast<const float4*>(g_proto + (size_t)row*Fn);
        float s = 0.f;
        #pragma unroll 4
        for (int it = 0; it < 16; it++){
            float4 v = pr[lane + 32*it];
            s += v.x*v.x + v.y*v.y + v.z*v.z + v.w*v.w;
        }
        s = wredsum(s);
        if (!lane) g_ninv[row] = 1.f / fmaxf(sqrtf(s), 1e-6f);
    }
    gsync();

    // ---- P4: cosine matrix (warp per pair) ----
    for (int pair = gw; pair < Cn*Cn; pair += NWARP){
        int i = pair / Cn, j = pair - i*Cn;
        const float4* pi = reinterpret_cast<const float4*>(g_proto + (size_t)i*Fn);
        const float4* pj = reinterpret_cast<const float4*>(g_proto + (size_t)j*Fn);
        float s = 0.f;
        #pragma unroll 4
        for (int it = 0; it < 16; it++){
            float4 a = pi[lane + 32*it], b2 = pj[lane + 32*it];
            s += a.x*b2.x + a.y*b2.y + a.z*b2.z + a.w*b2.w;
        }
        s = wredsum(s);
        if (!lane) g_cos[pair] = fminf(fmaxf(s*g_ninv[i]*g_ninv[j], -1.f), 1.f);
    }
    gsync();

    // ---- P5: T1 partials  (split-K=8, n-chunk=16, W staged in smem) ----
    {
        int kg = bid >> 4, nc = bid & 15;
        int kbase = kg*256, n0 = nc*16;
        for (int r = tid; r < 4096; r += T){
            int kk = r >> 4, nn = r & 15;
            sm[r] = pp_w1[(size_t)(kbase+kk)*HIDn + n0 + nn];
        }
        __syncthreads();
        int nn = tid & 15, cg = tid >> 4;          // cg 0..15
        float acc[5] = {0,0,0,0,0};
        for (int kk = 0; kk < 256; kk++){
            float w = sm[kk*16 + nn];
            #pragma unroll
            for (int q = 0; q < 5; q++)
                acc[q] += g_proto[(size_t)(cg + q*16)*Fn + kbase + kk]*w;
        }
        #pragma unroll
        for (int q = 0; q < 5; q++)
            g_part[(size_t)kg*Cn*HIDn + (cg + q*16)*HIDn + n0 + nn] = acc[q];
    }
    gsync();

    // ---- P6: T1 reduce + relu ----
    for (int idx = g; idx < Cn*HIDn; idx += NT){
        float s = pp_b1[idx & 255];
        #pragma unroll
        for (int kg = 0; kg < 8; kg++) s += g_part[kg*Cn*HIDn + idx];
        g_T1[idx] = fmaxf(s, 0.f);
    }
    gsync();

    // ---- P7: Hn = T1 @ pp_w2 + b2 ----
    for (int idx = g; idx < Cn*HIDn; idx += NT){
        int n = idx & 255, c = idx >> 8;
        const float* x = g_T1 + c*HIDn;
        float s = pp_b2[n];
        #pragma unroll 4
        for (int k = 0; k < HIDn; k++) s += x[k]*pp_w2[(size_t)k*HIDn + n];
        g_Hn[idx] = s;
    }
    gsync();

    // ---- P8: Zd = relu(Hn @ ed_w + ed_b) ----
    for (int idx = g; idx < Cn*EDDn; idx += NT){
        int n = idx & 63, c = idx >> 6;
        const float* x = g_Hn + c*HIDn;
        float s = ed_b[n];
        #pragma unroll 4
        for (int k = 0; k < HIDn; k++) s += x[k]*ed_w[(size_t)k*EDDn + n];
        g_Zd[idx] = fmaxf(s, 0.f);
    }
    gsync();

    // ---- P9: fused edge MLP (16 edges per tile, tiles looped over blocks) ----
    {
        float* ef = sm;               // 16*260
        float* e1 = sm + 4160;        // 16*128
        float* e2 = sm + 6208;        // 16*64
        for (int tile = bid; tile < 400; tile += G){
            int e0 = tile*16;
            #pragma unroll
            for (int rep = 0; rep < 4; rep++){
                int eo = rep*4 + (tid >> 6);
                int l = tid & 63;
                int e = e0 + eo, i = e/Cn, j = e - i*Cn;
                float zi = g_Zd[i*EDDn + l];
                float zj = g_Zd[j*EDDn + l];
                ef[eo*260 + l]       = zi;
                ef[eo*260 + 64 + l]  = zj;
                ef[eo*260 + 128 + l] = fabsf(zi - zj);
                ef[eo*260 + 192 + l] = zi*zj;
                if (!l){
                    ef[eo*260 + 256] = g_cos[e];
                    ef[eo*260 + 257] = g_freq[i];
                    ef[eo*260 + 258] = g_freq[j];
                }
            }
            __syncthreads();
            {   // layer1: 259 -> 128
                int n = tid & 127, eg = tid >> 7;
                float bv = em_b1[n];
                float acc[8];
                #pragma unroll
                for (int q = 0; q < 8; q++) acc[q] = bv;
                for (int k = 0; k < EINn; k++){
                    float w = em_w1[(size_t)k*128 + n];
                    #pragma unroll
                    for (int q = 0; q < 8; q++) acc[q] += ef[(eg*8+q)*260 + k]*w;
                }
                #pragma unroll
                for (int q = 0; q < 8; q++) e1[(eg*8+q)*128 + n] = fmaxf(acc[q], 0.f);
            }
            __syncthreads();
            {   // layer2: 128 -> 64
                int n = tid & 63, eg = tid >> 6;
                float bv = em_b2[n];
                float acc[4];
                #pragma unroll
                for (int q = 0; q < 4; q++) acc[q] = bv;
                for (int k = 0; k < 128; k++){
                    float w = em_w2[(size_t)k*64 + n];
                    #pragma unroll
                    for (int q = 0; q < 4; q++) acc[q] += e1[(eg*4+q)*128 + k]*w;
                }
                #pragma unroll
                for (int q = 0; q < 4; q++) e2[(eg*4+q)*64 + n] = fmaxf(acc[q], 0.f);
            }
            __syncthreads();
            {   // layer3: 64 -> 1
                int wid2 = tid >> 5;
                #pragma unroll
                for (int s2 = 0; s2 < 2; s2++){
                    int eo = wid2*2 + s2;
                    float v = e2[eo*64 + lane]*em_w3[lane]
                            + e2[eo*64 + 32 + lane]*em_w3[32 + lane];
                    v = wredsum(v);
                    if (!lane){
                        int e = e0 + eo;
                        float r = v + em_b3[0];
                        g_r[e] = r;
                        g_h[e] = pmi[e]*(1.f/2.5f) + r;
                    }
                }
            }
            __syncthreads();
        }
    }
    gsync();

    // ---- P10: wadj + row-normalized A (warp per row) ----
    for (int i = gw; i < Cn; i += NWARP){
        float w[3]; float s = 0.f;
        #pragma unroll
        for (int q = 0; q < 3; q++){
            int j = lane + q*32;
            float v = 0.f;
            if (j < Cn && j != i)
                v = 0.5f*(sigmoidf_(g_h[i*Cn+j]) + sigmoidf_(g_h[j*Cn+i]));
            w[q] = v; s += v;
        }
        s = wredsum(s);
        float inv = 1.f / fmaxf(s, 1e-6f);
        #pragma unroll
        for (int q = 0; q < 3; q++){
            int j = lane + q*32;
            if (j < Cn){ o_wadj[i*Cn+j] = w[q]; g_A[i*Cn+j] = w[q]*inv; }
        }
    }
    gsync();

    // ---- P11: GNN message step (block per row) ----
    if (bid < Cn){
        int i = bid, n = tid;
        float* sA = sm; float* az = sm + 80; float* m1 = sm + 336;
        if (n < Cn) sA[n] = g_A[i*Cn + n];
        __syncthreads();
        float acc = 0.f;
        for (int j = 0; j < Cn; j++) acc += sA[j]*g_Hn[j*HIDn + n];
        az[n] = acc;
        __syncthreads();
        acc = msg_b1[n];
        #pragma unroll 4
        for (int k = 0; k < HIDn; k++) acc += az[k]*msg_w1[(size_t)k*HIDn + n];
        m1[n] = fmaxf(acc, 0.f);
        __syncthreads();
        acc = msg_b2[n];
        #pragma unroll 4
        for (int k = 0; k < HIDn; k++) acc += m1[k]*msg_w2[(size_t)k*HIDn + n];
        g_Z[i*HIDn + n] = fmaxf(g_Hn[i*HIDn + n] + acc, 0.f);
    }
    gsync();

    // ---- P12: alpha = softplus(Z @ alpha_w + b)  (n-chunk=32 staged) ----
    if (bid < 64){
        int n0 = bid*32;
        for (int r = tid; r < 8192; r += T){
            int kk = r >> 5, nn = r & 31;
            sm[r] = alpha_w[(size_t)kk*Fn + n0 + nn];
        }
        __syncthreads();
        int nn = tid & 31, cg = tid >> 5;            // cg 0..7
        float acc[10];
        #pragma unroll
        for (int q = 0; q < 10; q++) acc[q] = 0.f;
        for (int kk = 0; kk < HIDn; kk++){
            float w = sm[kk*32 + nn];
            #pragma unroll
            for (int q = 0; q < 10; q++) acc[q] += g_Z[(cg + q*8)*HIDn + kk]*w;
        }
        float bv = alpha_b[n0 + nn];
        #pragma unroll
        for (int q = 0; q < 10; q++)
            g_awraw[(size_t)(cg + q*8)*Fn + n0 + nn] = softplusf_(acc[q] + bv);
    }
    gsync();

    // ---- P13: awnorm (warps 0..79)  +  dlog/refined (warps 512..591) ----
    for (int c = gw; c < Cn; c += NWARP){
        const float4* p = reinterpret_cast<const float4*>(g_awraw + (size_t)c*Fn);
        float s = 0.f;
        #pragma unroll 4
        for (int it = 0; it < 16; it++){ float4 v = p[lane + 32*it]; s += v.x+v.y+v.z+v.w; }
        s = wredsum(s);
        float inv = 1.f / fmaxf(s, 1e-6f);
        float4* q4 = reinterpret_cast<float4*>(o_aw + (size_t)c*Fn);
        #pragma unroll 4
        for (int it = 0; it < 16; it++){
            float4 v = p[lane + 32*it];
            v.x *= inv; v.y *= inv; v.z *= inv; v.w *= inv;
            q4[lane + 32*it] = v;
        }
    }
    {
        int wd = gw - 512;
        if (wd >= 0 && wd < Cn){
            int d = wd;
            float s = 0.f;
            for (int k = lane; k < HIDn; k += 32) s += g_Z[d*HIDn + k]*bw[k];
            s = wredsum(s);
            float dl = s + bb[0];
            if (!lane) o_dlog[d] = dl;
            int b = lane;  // 32 lanes = 32 batches
            float acc = 0.f;
            for (int c2 = 0; c2 < Cn; c2++)
                acc += g_probs[b*Cn + c2]*g_y[b*Cn + c2]*o_wadj[c2*Cn + d];
            int idx = b*Cn + d;
            float pos = g_y[idx]*acc;
            o_ref[idx] = cls[idx] + 0.5f*pos - 0.25f*(g_P[b] - pos) + dl;
        }
    }
    gsync();

    // ---- P14: losses (block 0 only) ----
    if (bid != 0) return;
    {
        int t = tid;
        float s_cls = 0.f, msum = 0.f;
        for (int idx = t; idx < Bn*Cn; idx += T){
            float tg = g_tgt[idx];
            float m = (tg != -1.f) ? 1.f : 0.f;
            float st = (m > 0.f) ? tg : 0.f;
            s_cls += bcef_(o_ref[idx], st)*m;
            msum += m;
        }
        float spb=0,snb=0,np=0,nn2=0,ne=0,sr=0,sw=0;
        for (int idx = t; idx < Cn*Cn; idx += T){
            int i = idx / Cn, j = idx - i*Cn;
            float emf = (i != j && g_present[i] > 0.f && g_present[j] > 0.f) ? 1.f : 0.f;
            float tt = sigmoidf_(pmi[idx]*(1.f/2.5f));
            float bce = bcef_(g_h[idx], tt);
            float posf = (tt > 0.5f) ? 1.f : 0.f;
            spb += bce*emf*posf;
            snb += bce*emf*(1.f - posf);
            np += posf*emf; nn2 += (1.f - posf)*emf; ne += emf;
            sr += fabsf(g_r[idx])*emf;
            sw += o_wadj[idx];
        }
        s_cls = bred_sm(s_cls, sm); msum = bred_sm(msum, sm);
        spb = bred_sm(spb, sm); snb = bred_sm(snb, sm);
        np = bred_sm(np, sm); nn2 = bred_sm(nn2, sm); ne = bred_sm(ne, sm);
        sr = bred_sm(sr, sm); sw = bred_sm(sw, sm);
        if (t == 0){
            float cls_loss = s_cls / fmaxf(msum, 1.f);
            float wp = fminf(fmaxf(fmaxf(nn2,1.f)/fmaxf(np,1.f), 1.f), 10.f);
            float ne_ = fmaxf(ne, 1.f);
            float edge_loss = (wp*spb + snb)/ne_;
            float r_reg = 0.001f*sr/ne_;
            float sparsity = sw * (1.f/(Cn*Cn));
            o_tot[0] = cls_loss + 0.1f*edge_loss + r_reg + 0.01f*sparsity;
        }
    }
}

// ---------------- cam: tf32 WMMA GEMM  cam[b] = aw[80x2048] @ feats[b][2048x1024]
__global__ void __launch_bounds__(256) k_cam(const float* __restrict__ aw,
                                             const float* __restrict__ feats){
    const int b  = blockIdx.y;
    const int n0 = blockIdx.x*128;
    const int t  = threadIdx.x;
    const int wid = t >> 5;
    __shared__ float As[80*36];
    __shared__ float Bs[32*132];
    wmma::fragment<wmma::accumulator,16,16,8,float> acc[5];
    #pragma unroll
    for (int m = 0; m < 5; m++) wmma::fill_fragment(acc[m], 0.f);
    const float* fb = feats + (size_t)b*Fn*HWn;
    for (int k0 = 0; k0 < Fn; k0 += 32){
        #pragma unroll
        for (int rr = 0; rr < 10; rr++){
            int idx = t + rr*256;
            int m = idx >> 5, kk = idx & 31;
            As[m*36 + kk] = aw[(size_t)m*Fn + k0 + kk];
        }
        #pragma unroll
        for (int rr = 0; rr < 4; rr++){
            int idx = t + rr*256;
            int kk = idx >> 5, j4 = idx & 31;
            float4 v = *reinterpret_cast<const float4*>(fb + (size_t)(k0+kk)*HWn + n0 + j4*4);
            *reinterpret_cast<float4*>(&Bs[kk*132 + j4*4]) = v;
        }
        __syncthreads();
        #pragma unroll
        for (int ks = 0; ks < 4; ks++){
            wmma::fragment<wmma::matrix_b,16,16,8,wmma::precision::tf32,wmma::row_major> bf;
            wmma::load_matrix_sync(bf, &Bs[ks*8*132 + wid*16], 132);
            #pragma unroll
            for (int e = 0; e < bf.num_elements; e++) bf.x[e] = wmma::__float_to_tf32(bf.x[e]);
            #pragma unroll
            for (int m = 0; m < 5; m++){
                wmma::fragment<wmma::matrix_a,16,16,8,wmma::precision::tf32,wmma::row_major> af;
                wmma::load_matrix_sync(af, &As[m*16*36 + ks*8], 36);
                #pragma unroll
                for (int e = 0; e < af.num_elements; e++) af.x[e] = wmma::__float_to_tf32(af.x[e]);
                wmma::mma_sync(acc[m], af, bf, acc[m]);
            }
        }
        __syncthreads();
    }
    #pragma unroll
    for (int m = 0; m < 5; m++)
        wmma::store_matrix_sync(&g_cam[((size_t)(b*Cn + m*16))*HWn + n0 + wid*16],
                                acc[m], HWn, wmma::mem_row_major);
}

// warp-per-(b,c) row: relu -> minmax -> normalize
__global__ void __launch_bounds__(256) k_camvis(float* __restrict__ o_cam){
    int row = (blockIdx.x*256 + threadIdx.x) >> 5;
    int lane = threadIdx.x & 31;
    if (row >= Bn*Cn) return;
    const float4* p = reinterpret_cast<const float4*>(g_cam + (size_t)row*HWn);
    float vals[32];
    float mn = 1e30f, mx = -1e30f;
    #pragma unroll
    for (int i = 0; i < 8; i++){
        float4 v = p[lane + 32*i];
        float a = fmaxf(v.x, 0.f), b = fmaxf(v.y, 0.f), c = fmaxf(v.z, 0.f), d = fmaxf(v.w, 0.f);
        vals[4*i] = a; vals[4*i+1] = b; vals[4*i+2] = c; vals[4*i+3] = d;
        mn = fminf(mn, fminf(fminf(a,b), fminf(c,d)));
        mx = fmaxf(mx, fmaxf(fmaxf(a,b), fmaxf(c,d)));
    }
    #pragma unroll
    for (int o = 16; o; o >>= 1){
        mn = fminf(mn, __shfl_xor_sync(0xffffffffu, mn, o));
        mx = fmaxf(mx, __shfl_xor_sync(0xffffffffu, mx, o));
    }
    float inv = 1.f / (mx - mn + 1e-6f);
    float4* q = reinterpret_cast<float4*>(o_cam + (size_t)row*HWn);
    #pragma unroll
    for (int i = 0; i < 8; i++){
        float4 v;
        v.x = (vals[4*i]   - mn)*inv;
        v.y = (vals[4*i+1] - mn)*inv;
        v.z = (vals[4*i+2] - mn)*inv;
        v.w = (vals[4*i+3] - mn)*inv;
        q[lane + 32*i] = v;
    }
}

// ---------------- host ----------------
extern "C" void kernel_launch(void* const* d_in, const int* in_sizes, int n_in,
                              void* d_out, int out_size){
    const float* feats   = (const float*)d_in[0];
    const float* cls     = (const float*)d_in[1];
    const int*   labels  = (const int*)  d_in[2];
    const float* pmi     = (const float*)d_in[3];
    const float* pp_w1   = (const float*)d_in[4];
    const float* pp_b1   = (const float*)d_in[5];
    const float* pp_w2   = (const float*)d_in[6];
    const float* pp_b2   = (const float*)d_in[7];
    const float* msg_w1  = (const float*)d_in[8];
    const float* msg_b1  = (const float*)d_in[9];
    const float* msg_w2  = (const float*)d_in[10];
    const float* msg_b2  = (const float*)d_in[11];
    const float* ed_w    = (const float*)d_in[12];
    const float* ed_b    = (const float*)d_in[13];
    const float* em_w1   = (const float*)d_in[14];
    const float* em_b1   = (const float*)d_in[15];
    const float* em_w2   = (const float*)d_in[16];
    const float* em_b2   = (const float*)d_in[17];
    const float* em_w3   = (const float*)d_in[18];
    const float* em_b3   = (const float*)d_in[19];
    const float* alpha_w = (const float*)d_in[20];
    const float* alpha_b = (const float*)d_in[21];
    const float* bias_w  = (const float*)d_in[22];
    const float* bias_b  = (const float*)d_in[23];

    float* out    = (float*)d_out;
    float* o_wadj = out + OFF_W;
    float* o_aw   = out + OFF_AW;
    float* o_dlog = out + OFF_DLOG;
    float* o_cam  = out + OFF_CAM;
    float* o_ref  = out + OFF_REF;
    float* o_tot  = out + OFF_TOT;

    k_mega<<<G, T>>>(feats, cls, labels, pmi,
                     pp_w1, pp_b1, pp_w2, pp_b2,
                     msg_w1, msg_b1, msg_w2, msg_b2,
                     ed_w, ed_b,
                     em_w1, em_b1, em_w2, em_b2, em_w3, em_b3,
                     alpha_w, alpha_b, bias_w, bias_b,
                     o_wadj, o_aw, o_dlog, o_ref, o_tot);
    k_cam<<<dim3(8, 32), 256>>>(o_aw, feats);
    k_camvis<<<320, 256>>>(o_cam);

    (void)in_sizes; (void)n_in; (void)out_size;
}

// round 7
// speedup vs baseline: 1.5353x; 1.0989x over previous
#include <cuda_runtime.h>
#include <mma.h>
#include <cstdint>

using namespace nvcuda;

#define Bn   32
#define Cn   80
#define Fn   2048
#define HWn  1024
#define HIDn 256
#define EDDn 64
#define EINn 259

#define G    128
#define T    512
#define NT   (G*T)
#define NWARP (NT/32)
#define KG   8

#define KSPLIT 4
#define CAMSZ  (Bn*Cn*HWn)

// output offsets (float32, flattened tuple order)
#define OFF_W    0
#define OFF_AW   6400
#define OFF_DLOG 170240
#define OFF_CAM  170320
#define OFF_REF  2791760
#define OFF_TOT  2794320

// ---------------- scratch (device globals; no allocations) ----------------
__device__ float g_probs[Bn*Cn], g_tgt[Bn*Cn], g_y[Bn*Cn];
__device__ float g_pooled[Bn*Fn];
__device__ float g_wsum[Cn], g_freq[Cn], g_present[Cn], g_P[Bn];
__device__ float g_proto[Cn*Fn];
__device__ float g_ninv[Cn];
__device__ float g_cos[Cn*Cn];
__device__ float g_part[KG*Cn*HIDn];
__device__ float g_T1[Cn*HIDn], g_Hn[Cn*HIDn];
__device__ float g_Zd[Cn*EDDn];
__device__ float g_r[Cn*Cn], g_h[Cn*Cn], g_A[Cn*Cn];
__device__ float g_Z[Cn*HIDn];
__device__ float g_awraw[Cn*Fn];
__device__ float g_cam[KSPLIT*CAMSZ];

// grid barrier state (monotonic generation -> re-entrant across replays)
__device__ volatile unsigned g_genv;
__device__ unsigned g_cntv;

// ---------------- helpers ----------------
__device__ __forceinline__ float wredsum(float v){
    #pragma unroll
    for (int o = 16; o; o >>= 1) v += __shfl_xor_sync(0xffffffffu, v, o);
    return v;
}
__device__ __forceinline__ float sigmoidf_(float x){ return 1.f/(1.f+expf(-x)); }
__device__ __forceinline__ float softplusf_(float x){ return fmaxf(x,0.f) + log1pf(expf(-fabsf(x))); }
__device__ __forceinline__ float bcef_(float x, float t){
    return fmaxf(x,0.f) - x*t + log1pf(expf(-fabsf(x)));
}

__device__ __forceinline__ void gsync(){
    __syncthreads();
    if (threadIdx.x == 0){
        unsigned my = g_genv;          // read BEFORE arrive
        __threadfence();               // release my writes; order the read
        if (atomicAdd(&g_cntv, 1u) == (unsigned)(G - 1)){
            atomicExch(&g_cntv, 0u);
            __threadfence();
            g_genv = my + 1u;
        } else {
            while (g_genv == my) { __nanosleep(64); }
        }
        __threadfence();               // acquire
    }
    __syncthreads();
}

__device__ __forceinline__ float bred_sm(float v, float* red){
    int t = threadIdx.x;
    red[t] = v; __syncthreads();
    for (int o = T/2; o; o >>= 1){ if (t < o) red[t] += red[t+o]; __syncthreads(); }
    float s = red[0]; __syncthreads();
    return s;
}

// ============================ MEGA KERNEL ============================
__global__ void __launch_bounds__(T) k_mega(
    const float* __restrict__ feats, const float* __restrict__ cls,
    const int*   __restrict__ lab,   const float* __restrict__ pmi,
    const float* __restrict__ pp_w1, const float* __restrict__ pp_b1,
    const float* __restrict__ pp_w2, const float* __restrict__ pp_b2,
    const float* __restrict__ msg_w1, const float* __restrict__ msg_b1,
    const float* __restrict__ msg_w2, const float* __restrict__ msg_b2,
    const float* __restrict__ ed_w,  const float* __restrict__ ed_b,
    const float* __restrict__ em_w1, const float* __restrict__ em_b1,
    const float* __restrict__ em_w2, const float* __restrict__ em_b2,
    const float* __restrict__ em_w3, const float* __restrict__ em_b3,
    const float* __restrict__ alpha_w, const float* __restrict__ alpha_b,
    const float* __restrict__ bw,    const float* __restrict__ bb,
    float* __restrict__ o_wadj, float* __restrict__ o_aw,
    float* __restrict__ o_dlog, float* __restrict__ o_ref, float* __restrict__ o_tot)
{
    __shared__ float sm[8448];   // 33 KB scratch, reused per phase
    const int tid  = threadIdx.x;
    const int bid  = blockIdx.x;
    const int g    = bid*T + tid;
    const int gw   = g >> 5;
    const int lane = tid & 31;

    // ---- P0: probs/tgt/y + adaptive pool (row-pairs for 2x MLP) ----
    for (int idx = g; idx < Bn*Cn; idx += NT){
        g_probs[idx] = sigmoidf_(cls[idx]);
        float tg = (float)lab[idx];
        g_tgt[idx] = tg;
        g_y[idx] = fmaxf(tg, 0.f);
    }
    for (int row = gw*2; row < Bn*Fn; row += NWARP*2){
        const float4* p0 = reinterpret_cast<const float4*>(feats + (size_t)row*HWn);
        const float4* p1 = reinterpret_cast<const float4*>(feats + (size_t)(row+1)*HWn);
        float s0 = 0.f, s1 = 0.f;
        #pragma unroll
        for (int i = 0; i < 8; i++){
            float4 a = p0[lane + 32*i];
            float4 b = p1[lane + 32*i];
            s0 += (a.x+a.y)+(a.z+a.w);
            s1 += (b.x+b.y)+(b.z+b.w);
        }
        s0 = wredsum(s0); s1 = wredsum(s1);
        if (!lane){ g_pooled[row] = s0*(1.f/1024.f); g_pooled[row+1] = s1*(1.f/1024.f); }
    }
    gsync();

    // ---- P1: stats ----
    if (g < Cn){
        float s = 0.f, mx = 0.f;
        #pragma unroll 4
        for (int b = 0; b < Bn; b++){ s += g_probs[b*Cn+g]; mx = fmaxf(mx, g_y[b*Cn+g]); }
        g_wsum[g] = fmaxf(s, 1e-6f);
        g_freq[g] = s * (1.f/Bn);
        g_present[g] = (mx > 0.f) ? 1.f : 0.f;
    } else if (g < Cn + Bn){
        int b = g - Cn; float s = 0.f;
        for (int c = 0; c < Cn; c++) s += g_probs[b*Cn+c];
        g_P[b] = s;
    }
    gsync();

    // ---- P2: prototypes (f-parallel; probs staged in smem) ----
    for (int idx = tid; idx < Bn*Cn; idx += T) sm[idx] = g_probs[idx];
    for (int idx = tid; idx < Cn;   idx += T) sm[Bn*Cn + idx] = 1.f / g_wsum[idx];
    __syncthreads();
    for (int idx = g; idx < Cn*Fn; idx += NT){
        int f = idx & (Fn-1), c = idx >> 11;
        float a = 0.f;
        #pragma unroll
        for (int b = 0; b < Bn; b++) a += sm[b*Cn + c]*g_pooled[b*Fn + f];
        g_proto[idx] = a * sm[Bn*Cn + c];
    }
    gsync();

    // ---- P3: row inv-norms ----
    for (int row = gw; row < Cn; row += NWARP){
        const float4* pr = reinterpret_cast<const float4*>(g_proto + (size_t)row*Fn);
        float s = 0.f;
        #pragma unroll 4
        for (int it = 0; it < 16; it++){
            float4 v = pr[lane + 32*it];
            s += v.x*v.x + v.y*v.y + v.z*v.z + v.w*v.w;
        }
        s = wredsum(s);
        if (!lane) g_ninv[row] = 1.f / fmaxf(sqrtf(s), 1e-6f);
    }
    gsync();

    // ---- P4: cosine matrix (warp per pair) ----
    for (int pair = gw; pair < Cn*Cn; pair += NWARP){
        int i = pair / Cn, j = pair - i*Cn;
        const float4* pi = reinterpret_cast<const float4*>(g_proto + (size_t)i*Fn);
        const float4* pj = reinterpret_cast<const float4*>(g_proto + (size_t)j*Fn);
        float s = 0.f;
        #pragma unroll 4
        for (int it = 0; it < 16; it++){
            float4 a = pi[lane + 32*it], b2 = pj[lane + 32*it];
            s += a.x*b2.x + a.y*b2.y + a.z*b2.z + a.w*b2.w;
        }
        s = wredsum(s);
        if (!lane) g_cos[pair] = fminf(fmaxf(s*g_ninv[i]*g_ninv[j], -1.f), 1.f);
    }
    gsync();

    // ---- P5: T1 partials (split-K=8 x n-chunk=16 = 128 blocks, W staged) ----
    {
        int kg = bid >> 4, nc = bid & 15;
        int kbase = kg*256, n0 = nc*16;
        for (int r = tid; r < 4096; r += T){
            int kk = r >> 4, nn = r & 15;
            sm[r] = pp_w1[(size_t)(kbase+kk)*HIDn + n0 + nn];
        }
        __syncthreads();
        int nn = tid & 15, cg = tid >> 4;          // cg 0..31
        int c2 = (cg < 16) ? cg + 64 : cg;         // safe 3rd-row index
        float a0 = 0.f, a1 = 0.f, a2 = 0.f;
        for (int kk = 0; kk < 256; kk++){
            float w = sm[kk*16 + nn];
            a0 += g_proto[(size_t)cg*Fn + kbase + kk]*w;
            a1 += g_proto[(size_t)(cg+32)*Fn + kbase + kk]*w;
            a2 += g_proto[(size_t)c2*Fn + kbase + kk]*w;
        }
        g_part[(size_t)kg*Cn*HIDn + cg*HIDn + n0 + nn]      = a0;
        g_part[(size_t)kg*Cn*HIDn + (cg+32)*HIDn + n0 + nn] = a1;
        if (cg < 16)
            g_part[(size_t)kg*Cn*HIDn + (cg+64)*HIDn + n0 + nn] = a2;
        __syncthreads();
    }
    gsync();

    // ---- P6: T1 reduce + relu ----
    for (int idx = g; idx < Cn*HIDn; idx += NT){
        float s = pp_b1[idx & 255];
        #pragma unroll
        for (int kg = 0; kg < KG; kg++) s += g_part[kg*Cn*HIDn + idx];
        g_T1[idx] = fmaxf(s, 0.f);
    }
    gsync();

    // ---- P7: Hn = T1 @ pp_w2 + b2 ----
    for (int idx = g; idx < Cn*HIDn; idx += NT){
        int n = idx & 255, c = idx >> 8;
        const float* x = g_T1 + c*HIDn;
        float s = pp_b2[n];
        #pragma unroll 4
        for (int k = 0; k < HIDn; k++) s += x[k]*pp_w2[(size_t)k*HIDn + n];
        g_Hn[idx] = s;
    }
    gsync();

    // ---- P8: Zd = relu(Hn @ ed_w + ed_b) ----
    for (int idx = g; idx < Cn*EDDn; idx += NT){
        int n = idx & 63, c = idx >> 6;
        const float* x = g_Hn + c*HIDn;
        float s = ed_b[n];
        #pragma unroll 4
        for (int k = 0; k < HIDn; k++) s += x[k]*ed_w[(size_t)k*EDDn + n];
        g_Zd[idx] = fmaxf(s, 0.f);
    }
    gsync();

    // ---- P9: fused edge MLP (16 edges/tile, 400 tiles over 128 blocks) ----
    {
        float* ef = sm;               // 16*260
        float* e1 = sm + 4160;        // 16*128
        float* e2 = sm + 6208;        // 16*64
        for (int tile = bid; tile < 400; tile += G){
            int e0 = tile*16;
            #pragma unroll
            for (int rep = 0; rep < 2; rep++){
                int eo = rep*8 + (tid >> 6);   // 0..15
                int l = tid & 63;
                int e = e0 + eo, i = e/Cn, j = e - i*Cn;
                float zi = g_Zd[i*EDDn + l];
                float zj = g_Zd[j*EDDn + l];
                ef[eo*260 + l]       = zi;
                ef[eo*260 + 64 + l]  = zj;
                ef[eo*260 + 128 + l] = fabsf(zi - zj);
                ef[eo*260 + 192 + l] = zi*zj;
                if (!l){
                    ef[eo*260 + 256] = g_cos[e];
                    ef[eo*260 + 257] = g_freq[i];
                    ef[eo*260 + 258] = g_freq[j];
                }
            }
            __syncthreads();
            {   // layer1: 259 -> 128 (4 groups x 4 edges)
                int n = tid & 127, eg = tid >> 7;
                float bv = em_b1[n];
                float acc[4];
                #pragma unroll
                for (int q = 0; q < 4; q++) acc[q] = bv;
                for (int k = 0; k < EINn; k++){
                    float w = em_w1[(size_t)k*128 + n];
                    #pragma unroll
                    for (int q = 0; q < 4; q++) acc[q] += ef[(eg*4+q)*260 + k]*w;
                }
                #pragma unroll
                for (int q = 0; q < 4; q++) e1[(eg*4+q)*128 + n] = fmaxf(acc[q], 0.f);
            }
            __syncthreads();
            {   // layer2: 128 -> 64 (8 groups x 2 edges)
                int n = tid & 63, eg = tid >> 6;
                float bv = em_b2[n];
                float acc[2];
                #pragma unroll
                for (int q = 0; q < 2; q++) acc[q] = bv;
                for (int k = 0; k < 128; k++){
                    float w = em_w2[(size_t)k*64 + n];
                    #pragma unroll
                    for (int q = 0; q < 2; q++) acc[q] += e1[(eg*2+q)*128 + k]*w;
                }
                #pragma unroll
                for (int q = 0; q < 2; q++) e2[(eg*2+q)*64 + n] = fmaxf(acc[q], 0.f);
            }
            __syncthreads();
            {   // layer3: 64 -> 1 (16 warps, 1 edge each)
                int eo = tid >> 5;
                float v = e2[eo*64 + lane]*em_w3[lane]
                        + e2[eo*64 + 32 + lane]*em_w3[32 + lane];
                v = wredsum(v);
                if (!lane){
                    int e = e0 + eo;
                    float r = v + em_b3[0];
                    g_r[e] = r;
                    g_h[e] = pmi[e]*(1.f/2.5f) + r;
                }
            }
            __syncthreads();
        }
    }
    gsync();

    // ---- P10: wadj + row-normalized A (warp per row) ----
    for (int i = gw; i < Cn; i += NWARP){
        float w[3]; float s = 0.f;
        #pragma unroll
        for (int q = 0; q < 3; q++){
            int j = lane + q*32;
            float v = 0.f;
            if (j < Cn && j != i)
                v = 0.5f*(sigmoidf_(g_h[i*Cn+j]) + sigmoidf_(g_h[j*Cn+i]));
            w[q] = v; s += v;
        }
        s = wredsum(s);
        float inv = 1.f / fmaxf(s, 1e-6f);
        #pragma unroll
        for (int q = 0; q < 3; q++){
            int j = lane + q*32;
            if (j < Cn){ o_wadj[i*Cn+j] = w[q]; g_A[i*Cn+j] = w[q]*inv; }
        }
    }
    gsync();

    // ---- P11: GNN message step (block per row; first 256 threads active) ----
    if (bid < Cn){
        int i = bid, n = tid;
        float* sA = sm; float* az = sm + 80; float* m1 = sm + 336;
        if (n < Cn) sA[n] = g_A[i*Cn + n];
        __syncthreads();
        float acc = 0.f;
        if (n < HIDn){
            for (int j = 0; j < Cn; j++) acc += sA[j]*g_Hn[j*HIDn + n];
            az[n] = acc;
        }
        __syncthreads();
        if (n < HIDn){
            acc = msg_b1[n];
            #pragma unroll 4
            for (int k = 0; k < HIDn; k++) acc += az[k]*msg_w1[(size_t)k*HIDn + n];
            m1[n] = fmaxf(acc, 0.f);
        }
        __syncthreads();
        if (n < HIDn){
            acc = msg_b2[n];
            #pragma unroll 4
            for (int k = 0; k < HIDn; k++) acc += m1[k]*msg_w2[(size_t)k*HIDn + n];
            g_Z[i*HIDn + n] = fmaxf(g_Hn[i*HIDn + n] + acc, 0.f);
        }
    }
    gsync();

    // ---- P12: alpha = softplus(Z @ alpha_w + b)  (n-chunk=16, 128 blocks) ----
    {
        int n0 = bid*16;
        for (int r = tid; r < 4096; r += T){
            int kk = r >> 4, nn = r & 15;
            sm[r] = alpha_w[(size_t)kk*Fn + n0 + nn];
        }
        __syncthreads();
        int nn = tid & 15, cg = tid >> 4;            // cg 0..31
        int c2 = (cg < 16) ? cg + 64 : cg;           // safe 3rd-row index
        float a0 = 0.f, a1 = 0.f, a2 = 0.f;
        for (int kk = 0; kk < HIDn; kk++){
            float w = sm[kk*16 + nn];
            a0 += g_Z[cg*HIDn + kk]*w;
            a1 += g_Z[(cg+32)*HIDn + kk]*w;
            a2 += g_Z[c2*HIDn + kk]*w;
        }
        float bv = alpha_b[n0 + nn];
        g_awraw[(size_t)cg*Fn + n0 + nn]      = softplusf_(a0 + bv);
        g_awraw[(size_t)(cg+32)*Fn + n0 + nn] = softplusf_(a1 + bv);
        if (cg < 16)
            g_awraw[(size_t)(cg+64)*Fn + n0 + nn] = softplusf_(a2 + bv);
        __syncthreads();
    }
    gsync();

    // ---- P13: awnorm (warps 0..79)  +  dlog/refined (warps 1024..1103) ----
    for (int c = gw; c < Cn; c += NWARP){
        const float4* p = reinterpret_cast<const float4*>(g_awraw + (size_t)c*Fn);
        float s = 0.f;
        #pragma unroll 4
        for (int it = 0; it < 16; it++){ float4 v = p[lane + 32*it]; s += v.x+v.y+v.z+v.w; }
        s = wredsum(s);
        float inv = 1.f / fmaxf(s, 1e-6f);
        float4* q4 = reinterpret_cast<float4*>(o_aw + (size_t)c*Fn);
        #pragma unroll 4
        for (int it = 0; it < 16; it++){
            float4 v = p[lane + 32*it];
            v.x *= inv; v.y *= inv; v.z *= inv; v.w *= inv;
            q4[lane + 32*it] = v;
        }
    }
    {
        int wd = gw - 1024;
        if (wd >= 0 && wd < Cn){
            int d = wd;
            float s = 0.f;
            for (int k = lane; k < HIDn; k += 32) s += g_Z[d*HIDn + k]*bw[k];
            s = wredsum(s);
            float dl = s + bb[0];
            if (!lane) o_dlog[d] = dl;
            int b = lane;  // 32 lanes = 32 batches
            float acc = 0.f;
            for (int c2b = 0; c2b < Cn; c2b++)
                acc += g_probs[b*Cn + c2b]*g_y[b*Cn + c2b]*o_wadj[c2b*Cn + d];
            int idx = b*Cn + d;
            float pos = g_y[idx]*acc;
            o_ref[idx] = cls[idx] + 0.5f*pos - 0.25f*(g_P[b] - pos) + dl;
        }
    }
    gsync();

    // ---- P14: losses (block 0 only) ----
    if (bid != 0) return;
    {
        int t = tid;
        float s_cls = 0.f, msum = 0.f;
        for (int idx = t; idx < Bn*Cn; idx += T){
            float tg = g_tgt[idx];
            float m = (tg != -1.f) ? 1.f : 0.f;
            float st = (m > 0.f) ? tg : 0.f;
            s_cls += bcef_(o_ref[idx], st)*m;
            msum += m;
        }
        float spb=0,snb=0,np=0,nn2=0,ne=0,sr=0,sw=0;
        for (int idx = t; idx < Cn*Cn; idx += T){
            int i = idx / Cn, j = idx - i*Cn;
            float emf = (i != j && g_present[i] > 0.f && g_present[j] > 0.f) ? 1.f : 0.f;
            float tt = sigmoidf_(pmi[idx]*(1.f/2.5f));
            float bce = bcef_(g_h[idx], tt);
            float posf = (tt > 0.5f) ? 1.f : 0.f;
            spb += bce*emf*posf;
            snb += bce*emf*(1.f - posf);
            np += posf*emf; nn2 += (1.f - posf)*emf; ne += emf;
            sr += fabsf(g_r[idx])*emf;
            sw += o_wadj[idx];
        }
        s_cls = bred_sm(s_cls, sm); msum = bred_sm(msum, sm);
        spb = bred_sm(spb, sm); snb = bred_sm(snb, sm);
        np = bred_sm(np, sm); nn2 = bred_sm(nn2, sm); ne = bred_sm(ne, sm);
        sr = bred_sm(sr, sm); sw = bred_sm(sw, sm);
        if (t == 0){
            float cls_loss = s_cls / fmaxf(msum, 1.f);
            float wp = fminf(fmaxf(fmaxf(nn2,1.f)/fmaxf(np,1.f), 1.f), 10.f);
            float ne_ = fmaxf(ne, 1.f);
            float edge_loss = (wp*spb + snb)/ne_;
            float r_reg = 0.001f*sr/ne_;
            float sparsity = sw * (1.f/(Cn*Cn));
            o_tot[0] = cls_loss + 0.1f*edge_loss + r_reg + 0.01f*sparsity;
        }
    }
}

// ---------------- cam: tf32 WMMA, K-split over blockIdx.z ----------------
__global__ void __launch_bounds__(256) k_cam(const float* __restrict__ aw,
                                             const float* __restrict__ feats){
    const int b  = blockIdx.y;
    const int ks = blockIdx.z;
    const int n0 = blockIdx.x*128;
    const int t  = threadIdx.x;
    const int wid = t >> 5;
    __shared__ float As[80*36];
    __shared__ float Bs[32*132];
    wmma::fragment<wmma::accumulator,16,16,8,float> acc[5];
    #pragma unroll
    for (int m = 0; m < 5; m++) wmma::fill_fragment(acc[m], 0.f);
    const float* fb = feats + (size_t)b*Fn*HWn;
    const int kstart = ks*(Fn/KSPLIT);
    for (int k0 = kstart; k0 < kstart + Fn/KSPLIT; k0 += 32){
        #pragma unroll
        for (int rr = 0; rr < 10; rr++){
            int idx = t + rr*256;
            int m = idx >> 5, kk = idx & 31;
            As[m*36 + kk] = aw[(size_t)m*Fn + k0 + kk];
        }
        #pragma unroll
        for (int rr = 0; rr < 4; rr++){
            int idx = t + rr*256;
            int kk = idx >> 5, j4 = idx & 31;
            float4 v = *reinterpret_cast<const float4*>(fb + (size_t)(k0+kk)*HWn + n0 + j4*4);
            *reinterpret_cast<float4*>(&Bs[kk*132 + j4*4]) = v;
        }
        __syncthreads();
        #pragma unroll
        for (int kss = 0; kss < 4; kss++){
            wmma::fragment<wmma::matrix_b,16,16,8,wmma::precision::tf32,wmma::row_major> bf;
            wmma::load_matrix_sync(bf, &Bs[kss*8*132 + wid*16], 132);
            #pragma unroll
            for (int e = 0; e < bf.num_elements; e++) bf.x[e] = wmma::__float_to_tf32(bf.x[e]);
            #pragma unroll
            for (int m = 0; m < 5; m++){
                wmma::fragment<wmma::matrix_a,16,16,8,wmma::precision::tf32,wmma::row_major> af;
                wmma::load_matrix_sync(af, &As[m*16*36 + kss*8], 36);
                #pragma unroll
                for (int e = 0; e < af.num_elements; e++) af.x[e] = wmma::__float_to_tf32(af.x[e]);
                wmma::mma_sync(acc[m], af, bf, acc[m]);
            }
        }
        __syncthreads();
    }
    #pragma unroll
    for (int m = 0; m < 5; m++)
        wmma::store_matrix_sync(&g_cam[(size_t)ks*CAMSZ + ((size_t)(b*Cn + m*16))*HWn + n0 + wid*16],
                                acc[m], HWn, wmma::mem_row_major);
}

// warp-per-(b,c) row: sum K-partials -> relu -> minmax -> normalize
__global__ void __launch_bounds__(256) k_camvis(float* __restrict__ o_cam){
    int row = (blockIdx.x*256 + threadIdx.x) >> 5;
    int lane = threadIdx.x & 31;
    if (row >= Bn*Cn) return;
    const float4* p0 = reinterpret_cast<const float4*>(g_cam + 0*(size_t)CAMSZ + (size_t)row*HWn);
    const float4* p1 = reinterpret_cast<const float4*>(g_cam + 1*(size_t)CAMSZ + (size_t)row*HWn);
    const float4* p2 = reinterpret_cast<const float4*>(g_cam + 2*(size_t)CAMSZ + (size_t)row*HWn);
    const float4* p3 = reinterpret_cast<const float4*>(g_cam + 3*(size_t)CAMSZ + (size_t)row*HWn);
    float vals[32];
    float mn = 1e30f, mx = -1e30f;
    #pragma unroll
    for (int i = 0; i < 8; i++){
        float4 a = p0[lane + 32*i], b = p1[lane + 32*i];
        float4 c = p2[lane + 32*i], d = p3[lane + 32*i];
        float x0 = fmaxf((a.x+b.x)+(c.x+d.x), 0.f);
        float x1 = fmaxf((a.y+b.y)+(c.y+d.y), 0.f);
        float x2 = fmaxf((a.z+b.z)+(c.z+d.z), 0.f);
        float x3 = fmaxf((a.w+b.w)+(c.w+d.w), 0.f);
        vals[4*i] = x0; vals[4*i+1] = x1; vals[4*i+2] = x2; vals[4*i+3] = x3;
        mn = fminf(mn, fminf(fminf(x0,x1), fminf(x2,x3)));
        mx = fmaxf(mx, fmaxf(fmaxf(x0,x1), fmaxf(x2,x3)));
    }
    #pragma unroll
    for (int o = 16; o; o >>= 1){
        mn = fminf(mn, __shfl_xor_sync(0xffffffffu, mn, o));
        mx = fmaxf(mx, __shfl_xor_sync(0xffffffffu, mx, o));
    }
    float inv = 1.f / (mx - mn + 1e-6f);
    float4* q = reinterpret_cast<float4*>(o_cam + (size_t)row*HWn);
    #pragma unroll
    for (int i = 0; i < 8; i++){
        float4 v;
        v.x = (vals[4*i]   - mn)*inv;
        v.y = (vals[4*i+1] - mn)*inv;
        v.z = (vals[4*i+2] - mn)*inv;
        v.w = (vals[4*i+3] - mn)*inv;
        q[lane + 32*i] = v;
    }
}

// ---------------- host ----------------
extern "C" void kernel_launch(void* const* d_in, const int* in_sizes, int n_in,
                              void* d_out, int out_size){
    const float* feats   = (const float*)d_in[0];
    const float* cls     = (const float*)d_in[1];
    const int*   labels  = (const int*)  d_in[2];
    const float* pmi     = (const float*)d_in[3];
    const float* pp_w1   = (const float*)d_in[4];
    const float* pp_b1   = (const float*)d_in[5];
    const float* pp_w2   = (const float*)d_in[6];
    const float* pp_b2   = (const float*)d_in[7];
    const float* msg_w1  = (const float*)d_in[8];
    const float* msg_b1  = (const float*)d_in[9];
    const float* msg_w2  = (const float*)d_in[10];
    const float* msg_b2  = (const float*)d_in[11];
    const float* ed_w    = (const float*)d_in[12];
    const float* ed_b    = (const float*)d_in[13];
    const float* em_w1   = (const float*)d_in[14];
    const float* em_b1   = (const float*)d_in[15];
    const float* em_w2   = (const float*)d_in[16];
    const float* em_b2   = (const float*)d_in[17];
    const float* em_w3   = (const float*)d_in[18];
    const float* em_b3   = (const float*)d_in[19];
    const float* alpha_w = (const float*)d_in[20];
    const float* alpha_b = (const float*)d_in[21];
    const float* bias_w  = (const float*)d_in[22];
    const float* bias_b  = (const float*)d_in[23];

    float* out    = (float*)d_out;
    float* o_wadj = out + OFF_W;
    float* o_aw   = out + OFF_AW;
    float* o_dlog = out + OFF_DLOG;
    float* o_cam  = out + OFF_CAM;
    float* o_ref  = out + OFF_REF;
    float* o_tot  = out + OFF_TOT;

    k_mega<<<G, T>>>(feats, cls, labels, pmi,
                     pp_w1, pp_b1, pp_w2, pp_b2,
                     msg_w1, msg_b1, msg_w2, msg_b2,
                     ed_w, ed_b,
                     em_w1, em_b1, em_w2, em_b2, em_w3, em_b3,
                     alpha_w, alpha_b, bias_w, bias_b,
                     o_wadj, o_aw, o_dlog, o_ref, o_tot);
    k_cam<<<dim3(8, 32, KSPLIT), 256>>>(o_aw, feats);
    k_camvis<<<320, 256>>>(o_cam);

    (void)in_sizes; (void)n_in; (void)out_size;
}